// round 10
// baseline (speedup 1.0000x reference)
#include <cuda_runtime.h>
#include <cuda_fp16.h>
#include <math.h>

#define N_NODES 20000
#define E_EDGES 320000
#define ET      (E_EDGES + N_NODES)   // 340000
#define IN_DIM  256
#define HID     64
#define NH      4
#define C       64
#define HC      256
#define DFF     128
#define NL      4

typedef unsigned long long u64t;

// packed f32x2 helpers (FFMA2 path — ptxas never emits it from C++)
#define FMA2(d, a, b) asm("fma.rn.f32x2 %0, %1, %2, %0;" : "+l"(d) : "l"(a), "l"(b))
__device__ __forceinline__ float2 upk2(u64t v) {
    float2 f; asm("mov.b64 {%0, %1}, %2;" : "=f"(f.x), "=f"(f.y) : "l"(v)); return f;
}

// ---------------- static scratch (no cudaMalloc allowed) -----------------------
__device__ __half g_xh_h[N_NODES * HC];  // 10.2 MB fp16 messages (L2-resident)
__device__ float  g_as [N_NODES * NH];
__device__ float  g_ad [N_NODES * NH];
__device__ float  g_out[N_NODES * HC];
__device__ int    g_off[N_NODES + 1];
__device__ int    g_cur[N_NODES];
__device__ int    g_srcl[ET];            // CSR-by-dst: src node per slot

// transposed weights: row j = contiguous K column for output channel j
#define S_WE (IN_DIM * HID)              // 16384
#define S_WC (NL * HC * HID)             // 65536
#define S_W1 (NL * DFF * HC)             // 131072
#define S_W2 (NL * HID * DFF)            // 32768
__device__ __align__(16) float g_WeT[S_WE];   // [j*256 + k]
__device__ __align__(16) float g_WcT[S_WC];   // [l*16384 + j*64 + k]
__device__ __align__(16) float g_W1T[S_W1];   // [l*32768 + j*256 + k]
__device__ __align__(16) float g_W2T[S_W2];   // [l*8192  + j*128 + k]

// one-shot weight transpose (launch #1 each call; ~246K threads)
__global__ void k_wtrans(const float* __restrict__ We, const float* __restrict__ Wc,
                         const float* __restrict__ W1, const float* __restrict__ W2) {
    int t = blockIdx.x * blockDim.x + threadIdx.x;
    if (t < S_WE) {
        int j = t >> 8, k = t & 255;
        g_WeT[t] = We[k * HID + j];
    }
    int u = t - S_WE;
    if (u >= 0 && u < S_WC) {
        int l = u >> 14, r = u & 16383;
        int j = r >> 6, k = r & 63;
        g_WcT[u] = Wc[l * (HID * HC) + k * HC + j];
    }
    int v = u - S_WC;
    if (v >= 0 && v < S_W1) {
        int l = v >> 15, r = v & 32767;
        int j = r >> 8, k = r & 255;
        g_W1T[v] = W1[l * (HC * DFF) + k * DFF + j];
    }
    int w = v - S_W1;
    if (w >= 0 && w < S_W2) {
        int l = w >> 13, r = w & 8191;
        int j = r >> 7, k = r & 127;
        g_W2T[w] = W2[l * (DFF * HID) + k * HID + j];
    }
}

// ================= CSR construction (graph is layer-invariant) =================
__global__ void k_csr_init() {
    int i = blockIdx.x * blockDim.x + threadIdx.x;
    if (i < N_NODES) g_cur[i] = 1;       // self loop pre-counted
}

__global__ void k_csr_count(const int* __restrict__ ei) {
    int e = blockIdx.x * blockDim.x + threadIdx.x;
    if (e < E_EDGES) atomicAdd(&g_cur[ei[E_EDGES + e]], 1);
}

__global__ void k_csr_scan() {
    __shared__ int ps[1024];
    const int CH = 20;
    int t = threadIdx.x;
    int base = t * CH;
    int mysum = 0;
    for (int i = 0; i < CH; i++) { int idx = base + i; if (idx < N_NODES) mysum += g_cur[idx]; }
    ps[t] = mysum;
    __syncthreads();
    for (int d = 1; d < 1024; d <<= 1) {
        int v = (t >= d) ? ps[t - d] : 0;
        __syncthreads();
        ps[t] += v;
        __syncthreads();
    }
    int run = ps[t] - mysum;
    for (int i = 0; i < CH; i++) {
        int idx = base + i;
        if (idx < N_NODES) { int deg = g_cur[idx]; g_off[idx] = run; g_cur[idx] = run; run += deg; }
    }
    if (t == 1023) g_off[N_NODES] = ps[1023];
}

__global__ void k_csr_fill(const int* __restrict__ ei) {
    int e = blockIdx.x * blockDim.x + threadIdx.x;
    if (e >= ET) return;
    int src, dst;
    if (e < E_EDGES) { src = ei[e]; dst = ei[E_EDGES + e]; }
    else             { src = dst = e - E_EDGES; }
    int pos = atomicAdd(&g_cur[dst], 1);
    g_srcl[pos] = src;
}

// ====== dense kernels: FFMA2, transposed vectorized weight loads ==============

#define LOADW(wp, base, kc) do {                                   \
    ulonglong2 _w0 = (base)[(kc) * 2];                             \
    ulonglong2 _w1 = (base)[(kc) * 2 + 1];                         \
    wp[0] = _w0.x; wp[1] = _w0.y; wp[2] = _w1.x; wp[3] = _w1.y;    \
} while (0)

// h = (x @ We + be) * 8.  block 256; 16 nodes.  thread = (ch j, j+32) x 2 nodes
__global__ void __launch_bounds__(256, 4)
k_embed(const float* __restrict__ x, const float* __restrict__ be, float* __restrict__ h) {
    int t = threadIdx.x;
    int jp = t & 31, g = t >> 5;               // g 0..7 -> nodes g*2, g*2+1
    int n0 = blockIdx.x * 16;
    __shared__ __align__(16) float4 xs[16 * 64];   // 16 KB
#pragma unroll
    for (int q = 0; q < 4; q++) {
        int fi = t + q * 256;
        int row = fi >> 6, c4 = fi & 63;
        xs[fi] = *(const float4*)(x + (size_t)(n0 + row) * IN_DIM + c4 * 4);
    }
    __syncthreads();
    const ulonglong2* wAp = (const ulonglong2*)(g_WeT + jp * IN_DIM);
    const ulonglong2* wBp = (const ulonglong2*)(g_WeT + (jp + 32) * IN_DIM);
    u64t accA[2] = {0ULL, 0ULL}, accB[2] = {0ULL, 0ULL};
#pragma unroll 1
    for (int kc = 0; kc < 32; kc++) {          // K=256 in chunks of 8
        u64t wpA[4], wpB[4];
        LOADW(wpA, wAp, kc);
        LOADW(wpB, wBp, kc);
#pragma unroll
        for (int k4 = 0; k4 < 2; k4++) {
#pragma unroll
            for (int n = 0; n < 2; n++) {
                ulonglong2 v = ((const ulonglong2*)xs)[(g * 2 + n) * 64 + kc * 2 + k4];
                FMA2(accA[n], wpA[2 * k4],     v.x);
                FMA2(accA[n], wpA[2 * k4 + 1], v.y);
                FMA2(accB[n], wpB[2 * k4],     v.x);
                FMA2(accB[n], wpB[2 * k4 + 1], v.y);
            }
        }
    }
    float bA = be[jp], bB = be[jp + 32];
#pragma unroll
    for (int n = 0; n < 2; n++) {
        float2 fa = upk2(accA[n]), fb = upk2(accB[n]);
        h[(size_t)(n0 + g * 2 + n) * HID + jp]      = (fa.x + fa.y + bA) * 8.0f;
        h[(size_t)(n0 + g * 2 + n) * HID + jp + 32] = (fb.x + fb.y + bB) * 8.0f;
    }
}

// xh = h @ Wc (fp16) + a_s/a_d.  block 256; 32 nodes/block.
// thread = (ch jp, jp+128) x node-group ng of 16
__global__ void __launch_bounds__(256, 2)
k_xh_att(const float* __restrict__ h, int l,
         const float* __restrict__ att_src, const float* __restrict__ att_dst) {
    int t = threadIdx.x;
    int jp = t & 127, ng = t >> 7;             // channels jp, jp+128; nodes ng*16..+16
    int w = t >> 5, lane = t & 31;
    int n0 = blockIdx.x * 32;
    const float* WcT = g_WcT + (size_t)l * HC * HID;
    __shared__ __align__(16) float4 xs[32 * 16];   // 8 KB
    __shared__ float spA[8][16], dpA[8][16], spB[8][16], dpB[8][16];
#pragma unroll
    for (int q = 0; q < 2; q++) {
        int fi = t + q * 256;
        int row = fi >> 4, c4 = fi & 15;
        xs[fi] = *(const float4*)(h + (size_t)(n0 + row) * HID + c4 * 4);
    }
    __syncthreads();
    const ulonglong2* wAp = (const ulonglong2*)(WcT + jp * HID);
    const ulonglong2* wBp = (const ulonglong2*)(WcT + (jp + 128) * HID);
    u64t accA[16], accB[16];
#pragma unroll
    for (int n = 0; n < 16; n++) { accA[n] = 0ULL; accB[n] = 0ULL; }
#pragma unroll 1
    for (int kc = 0; kc < 8; kc++) {           // K=64 in chunks of 8
        u64t wpA[4], wpB[4];
        LOADW(wpA, wAp, kc);
        LOADW(wpB, wBp, kc);
#pragma unroll
        for (int k4 = 0; k4 < 2; k4++) {
#pragma unroll
            for (int n = 0; n < 16; n++) {
                ulonglong2 v = ((const ulonglong2*)xs)[(ng * 16 + n) * 16 + kc * 2 + k4];
                FMA2(accA[n], wpA[2 * k4],     v.x);
                FMA2(accA[n], wpA[2 * k4 + 1], v.y);
                FMA2(accB[n], wpB[2 * k4],     v.x);
                FMA2(accB[n], wpB[2 * k4 + 1], v.y);
            }
        }
    }
    float asA = att_src[jp], adA = att_dst[jp];
    float asB = att_src[jp + 128], adB = att_dst[jp + 128];
#pragma unroll
    for (int n = 0; n < 16; n++) {
        float2 fa = upk2(accA[n]), fb = upk2(accB[n]);
        float vA = fa.x + fa.y, vB = fb.x + fb.y;
        int node = n0 + ng * 16 + n;
        g_xh_h[(size_t)node * HC + jp]       = __float2half_rn(vA);
        g_xh_h[(size_t)node * HC + jp + 128] = __float2half_rn(vB);
        float sA = vA * asA, dA = vA * adA, sB = vB * asB, dB = vB * adB;
#pragma unroll
        for (int o = 16; o; o >>= 1) {
            sA += __shfl_xor_sync(0xffffffffu, sA, o);
            dA += __shfl_xor_sync(0xffffffffu, dA, o);
            sB += __shfl_xor_sync(0xffffffffu, sB, o);
            dB += __shfl_xor_sync(0xffffffffu, dB, o);
        }
        if (lane == 0) { spA[w][n] = sA; dpA[w][n] = dA; spB[w][n] = sB; dpB[w][n] = dB; }
    }
    __syncthreads();
    if (t < 128) {
        int node = t >> 2, hh = t & 3;         // local node 0..31, head 0..3
        int ngg = node >> 4, nn = node & 15;
        float s, d;
        if (hh < 2) {
            int wb = ngg * 4 + hh * 2;
            s = spA[wb][nn] + spA[wb + 1][nn];
            d = dpA[wb][nn] + dpA[wb + 1][nn];
        } else {
            int wb = ngg * 4 + (hh - 2) * 2;
            s = spB[wb][nn] + spB[wb + 1][nn];
            d = dpB[wb][nn] + dpB[wb + 1][nn];
        }
        g_as[(size_t)(n0 + node) * NH + hh] = s;
        g_ad[(size_t)(n0 + node) * NH + hh] = d;
    }
}

// GAT aggregation: one warp per dst node, online softmax, unroll-4 front-batched loads.
#define GAT_EDGE(Q, V) do {                                                       \
    float e = (Q) + ad; e = e > 0.f ? e : 0.2f * e;                               \
    if (e > m) {                                                                  \
        float corr = __expf(m - e);                                               \
        m = e; z *= corr;                                                         \
        a0 *= corr; a1 *= corr; a2 *= corr; a3 *= corr;                           \
        a4 *= corr; a5 *= corr; a6 *= corr; a7 *= corr;                           \
    }                                                                             \
    float wg = __expf(e - m);                                                     \
    z += wg;                                                                      \
    const __half2* hp = (const __half2*)&(V);                                     \
    float2 f0 = __half22float2(hp[0]), f1 = __half22float2(hp[1]);                \
    float2 f2 = __half22float2(hp[2]), f3 = __half22float2(hp[3]);                \
    a0 = fmaf(wg, f0.x, a0); a1 = fmaf(wg, f0.y, a1);                             \
    a2 = fmaf(wg, f1.x, a2); a3 = fmaf(wg, f1.y, a3);                             \
    a4 = fmaf(wg, f2.x, a4); a5 = fmaf(wg, f2.y, a5);                             \
    a6 = fmaf(wg, f3.x, a6); a7 = fmaf(wg, f3.y, a7);                             \
} while (0)

__global__ void k_gat(const float* __restrict__ bc) {
    int w = (blockIdx.x * blockDim.x + threadIdx.x) >> 5;
    if (w >= N_NODES) return;
    int lane = threadIdx.x & 31;
    int hh = lane >> 3;                  // head owning channels [lane*8, lane*8+8)
    int beg = g_off[w], end = g_off[w + 1];
    float ad = g_ad[w * NH + hh];
    float m = -INFINITY, z = 0.f;
    float a0 = 0, a1 = 0, a2 = 0, a3 = 0, a4 = 0, a5 = 0, a6 = 0, a7 = 0;
    int p = beg;
    for (; p + 4 <= end; p += 4) {       // MLP=4 front-batched
        int s0 = g_srcl[p], s1 = g_srcl[p + 1], s2 = g_srcl[p + 2], s3 = g_srcl[p + 3];
        float q0 = g_as[s0 * NH + hh];
        float q1 = g_as[s1 * NH + hh];
        float q2 = g_as[s2 * NH + hh];
        float q3 = g_as[s3 * NH + hh];
        uint4 v0 = *(const uint4*)(g_xh_h + (size_t)s0 * HC + lane * 8);
        uint4 v1 = *(const uint4*)(g_xh_h + (size_t)s1 * HC + lane * 8);
        uint4 v2 = *(const uint4*)(g_xh_h + (size_t)s2 * HC + lane * 8);
        uint4 v3 = *(const uint4*)(g_xh_h + (size_t)s3 * HC + lane * 8);
        GAT_EDGE(q0, v0);
        GAT_EDGE(q1, v1);
        GAT_EDGE(q2, v2);
        GAT_EDGE(q3, v3);
    }
    for (; p < end; p++) {
        int s0 = g_srcl[p];
        float q0 = g_as[s0 * NH + hh];
        uint4 v0 = *(const uint4*)(g_xh_h + (size_t)s0 * HC + lane * 8);
        GAT_EDGE(q0, v0);
    }
    float inv = 1.f / (z + 1e-16f);
    const float4* bcv = (const float4*)(bc + lane * 8);
    float4 c0 = bcv[0], c1 = bcv[1];
    float4 o0 = make_float4(fmaf(a0, inv, c0.x), fmaf(a1, inv, c0.y), fmaf(a2, inv, c0.z), fmaf(a3, inv, c0.w));
    float4 o1 = make_float4(fmaf(a4, inv, c1.x), fmaf(a5, inv, c1.y), fmaf(a6, inv, c1.z), fmaf(a7, inv, c1.w));
    float4* op = (float4*)(g_out + (size_t)w * HC + lane * 8);
    op[0] = o0; op[1] = o1;
}

// fused FFN: f = gelu(out@W1+b1)@W2 + b2;  h += layernorm(f).  256 thr; 32 nodes
__global__ void __launch_bounds__(256, 4)
k_ffn(int l, const float* __restrict__ b1, const float* __restrict__ b2,
      const float* __restrict__ lng, const float* __restrict__ lnb,
      float* __restrict__ h) {
    int t = threadIdx.x;
    int n0 = blockIdx.x * 32;
    const float* W1T = g_W1T + (size_t)l * DFF * HC;
    const float* W2T = g_W2T + (size_t)l * HID * DFF;
    __shared__ __align__(16) float pool[32 * 256]; // 32 KB
    __shared__ float2 stats[32];
    float4* xs = (float4*)pool;          // stage A view: 32 nodes x 64 float4
#pragma unroll
    for (int q = 0; q < 8; q++) {
        int fi = t + q * 256;
        int row = fi >> 6, c4 = fi & 63;
        xs[fi] = *(const float4*)(g_out + (size_t)(n0 + row) * HC + c4 * 4);
    }
    __syncthreads();
    // ---- stage A: ff = gelu(out @ W1 + b1); thread = (ch jp, jp+64) x 8 nodes ----
    int jp = t & 63, g = t >> 6;         // g 0..3 -> nodes g*8..+8
    const ulonglong2* wAp = (const ulonglong2*)(W1T + jp * HC);
    const ulonglong2* wBp = (const ulonglong2*)(W1T + (jp + 64) * HC);
    u64t accA[8], accB[8];
#pragma unroll
    for (int n = 0; n < 8; n++) { accA[n] = 0ULL; accB[n] = 0ULL; }
#pragma unroll 1
    for (int kc = 0; kc < 32; kc++) {    // K=256 in chunks of 8
        u64t wpA[4], wpB[4];
        LOADW(wpA, wAp, kc);
        LOADW(wpB, wBp, kc);
#pragma unroll
        for (int k4 = 0; k4 < 2; k4++) {
#pragma unroll
            for (int n = 0; n < 8; n++) {
                ulonglong2 v = ((const ulonglong2*)xs)[(g * 8 + n) * 64 + kc * 2 + k4];
                FMA2(accA[n], wpA[2 * k4],     v.x);
                FMA2(accA[n], wpA[2 * k4 + 1], v.y);
                FMA2(accB[n], wpB[2 * k4],     v.x);
                FMA2(accB[n], wpB[2 * k4 + 1], v.y);
            }
        }
    }
    __syncthreads();                     // all xs reads done; reuse pool for ff
    float* sff = pool;                   // 32 nodes x 128 floats = 16 KB
    {
        float bA = b1[jp], bB = b1[jp + 64];
#pragma unroll
        for (int n = 0; n < 8; n++) {
            float2 fa = upk2(accA[n]), fb = upk2(accB[n]);
            float vA = fa.x + fa.y + bA, vB = fb.x + fb.y + bB;
            sff[(g * 8 + n) * 128 + jp]      = 0.5f * vA * (1.0f + erff(vA * 0.70710678118654752f));
            sff[(g * 8 + n) * 128 + jp + 64] = 0.5f * vB * (1.0f + erff(vB * 0.70710678118654752f));
        }
    }
    __syncthreads();
    // ---- stage B: f = ff @ W2 + b2; thread = (ch jp2, jp2+32) x 4 nodes ----
    int jp2 = t & 31, g2 = t >> 5;       // g2 0..7 -> nodes g2*4..+4
    const ulonglong2* wA2 = (const ulonglong2*)(W2T + jp2 * DFF);
    const ulonglong2* wB2 = (const ulonglong2*)(W2T + (jp2 + 32) * DFF);
    u64t acc2A[4], acc2B[4];
#pragma unroll
    for (int r = 0; r < 4; r++) { acc2A[r] = 0ULL; acc2B[r] = 0ULL; }
#pragma unroll 1
    for (int kc = 0; kc < 16; kc++) {    // K=128 in chunks of 8
        u64t wpA[4], wpB[4];
        LOADW(wpA, wA2, kc);
        LOADW(wpB, wB2, kc);
#pragma unroll
        for (int k4 = 0; k4 < 2; k4++) {
#pragma unroll
            for (int r = 0; r < 4; r++) {
                ulonglong2 v = *(const ulonglong2*)&sff[(g2 * 4 + r) * 128 + kc * 8 + k4 * 4];
                FMA2(acc2A[r], wpA[2 * k4],     v.x);
                FMA2(acc2A[r], wpA[2 * k4 + 1], v.y);
                FMA2(acc2B[r], wpB[2 * k4],     v.x);
                FMA2(acc2B[r], wpB[2 * k4 + 1], v.y);
            }
        }
    }
    float fA[4], fB[4];
    {
        float bA = b2[jp2], bB = b2[jp2 + 32];
#pragma unroll
        for (int r = 0; r < 4; r++) {
            float2 fa = upk2(acc2A[r]), fb = upk2(acc2B[r]);
            fA[r] = fa.x + fa.y + bA;
            fB[r] = fb.x + fb.y + bB;
        }
    }
    // ---- LayerNorm over HID=64 per node (32 nodes, 8 threads/node) ----
    __syncthreads();                     // all sff reads done; reuse pool
    float* sln = pool;                   // stride-65 padded stash
#pragma unroll
    for (int r = 0; r < 4; r++) {
        sln[(g2 * 4 + r) * 65 + jp2]      = fA[r];
        sln[(g2 * 4 + r) * 65 + jp2 + 32] = fB[r];
    }
    __syncthreads();
    int node = t >> 3, part = t & 7;     // 8 threads per node
    float s = 0.f, sq = 0.f;
#pragma unroll
    for (int k = 0; k < 8; k++) {
        float v = sln[node * 65 + part * 8 + k];
        s += v; sq = fmaf(v, v, sq);
    }
    s  += __shfl_xor_sync(0xffffffffu, s, 1);  s  += __shfl_xor_sync(0xffffffffu, s, 2);  s  += __shfl_xor_sync(0xffffffffu, s, 4);
    sq += __shfl_xor_sync(0xffffffffu, sq, 1); sq += __shfl_xor_sync(0xffffffffu, sq, 2); sq += __shfl_xor_sync(0xffffffffu, sq, 4);
    if (part == 0) {
        float mean = s * (1.f / 64.f);
        stats[node] = make_float2(mean, sq * (1.f / 64.f) - mean * mean);
    }
    __syncthreads();
    float gA = lng[jp2], lA = lnb[jp2];
    float gB = lng[jp2 + 32], lB = lnb[jp2 + 32];
#pragma unroll
    for (int r = 0; r < 4; r++) {
        int nd = g2 * 4 + r;
        float2 st = stats[nd];
        float rinv = rsqrtf(st.y + 1e-5f);
        h[(size_t)(n0 + nd) * HID + jp2]      += (fA[r] - st.x) * rinv * gA + lA;
        h[(size_t)(n0 + nd) * HID + jp2 + 32] += (fB[r] - st.x) * rinv * gB + lB;
    }
}

// ================= driver ======================================================
extern "C" void kernel_launch(void* const* d_in, const int* in_sizes, int n_in,
                              void* d_out, int out_size) {
    const float* x       = (const float*)d_in[0];
    const int*   ei      = (const int*)  d_in[1];
    const float* We      = (const float*)d_in[2];
    const float* be      = (const float*)d_in[3];
    const float* Wc      = (const float*)d_in[4];
    const float* att_src = (const float*)d_in[5];
    const float* att_dst = (const float*)d_in[6];
    const float* bc      = (const float*)d_in[7];
    const float* W1      = (const float*)d_in[8];
    const float* b1      = (const float*)d_in[9];
    const float* W2      = (const float*)d_in[10];
    const float* b2      = (const float*)d_in[11];
    const float* ln_g    = (const float*)d_in[12];
    const float* ln_b    = (const float*)d_in[13];

    float* h = (float*)d_out;

    // k_xh_att stays the profiled (4th) launch.
    k_wtrans   <<<960, 256>>>(We, Wc, W1, W2);                 // 1
    k_csr_init <<<(N_NODES + 255) / 256, 256>>>();             // 2
    k_embed    <<<1250, 256>>>(x, be, h);                      // 3
    k_xh_att   <<<625, 256>>>(h, 0, att_src, att_dst);         // 4 (layer 0)
    k_csr_count<<<(E_EDGES + 255) / 256, 256>>>(ei);           // 5
    k_csr_scan <<<1, 1024>>>();                                // 6
    k_csr_fill <<<(ET + 255) / 256, 256>>>(ei);                // 7
    k_gat      <<<2500, 256>>>(bc);                            // 8 (layer 0)
    k_ffn      <<<625, 256>>>(0, b1, b2, ln_g, ln_b, h);       // 9 (layer 0)

    for (int l = 1; l < NL; l++) {
        k_xh_att<<<625, 256>>>(h, l, att_src + l * NH * C, att_dst + l * NH * C);
        k_gat   <<<2500, 256>>>(bc + l * HC);
        k_ffn   <<<625, 256>>>(l, b1 + l * DFF, b2 + l * HID,
                               ln_g + l * HID, ln_b + l * HID, h);
    }
}

// round 11
// speedup vs baseline: 2.3649x; 2.3649x over previous
#include <cuda_runtime.h>
#include <cuda_fp16.h>
#include <math.h>

#define N_NODES 20000
#define N_PAD   20032                 // padded rows for 64-node ffn tiles
#define E_EDGES 320000
#define ET      (E_EDGES + N_NODES)   // 340000
#define IN_DIM  256
#define HID     64
#define NH      4
#define C       64
#define HC      256
#define DFF     128
#define NL      4

typedef unsigned long long u64t;

// packed f32x2 helpers (FFMA2 path)
#define FMA2(d, a, b) asm("fma.rn.f32x2 %0, %1, %2, %0;" : "+l"(d) : "l"(a), "l"(b))
__device__ __forceinline__ u64t pk2(float lo, float hi) {
    u64t r; asm("mov.b64 %0, {%1, %2};" : "=l"(r) : "f"(lo), "f"(hi)); return r;
}
__device__ __forceinline__ float2 upk2(u64t v) {
    float2 f; asm("mov.b64 {%0, %1}, %2;" : "=f"(f.x), "=f"(f.y) : "l"(v)); return f;
}

// tensor-core helpers
#define LDSM4(a0, a1, a2, a3, addr) \
    asm volatile("ldmatrix.sync.aligned.m8n8.x4.shared.b16 {%0,%1,%2,%3}, [%4];" \
                 : "=r"(a0), "=r"(a1), "=r"(a2), "=r"(a3) : "r"(addr))
#define MMA16816(cc, a0, a1, a2, a3, b0, b1) \
    asm volatile("mma.sync.aligned.m16n8k16.row.col.f32.f16.f16.f32 " \
                 "{%0,%1,%2,%3}, {%4,%5,%6,%7}, {%8,%9}, {%0,%1,%2,%3};" \
                 : "+f"((cc)[0]), "+f"((cc)[1]), "+f"((cc)[2]), "+f"((cc)[3]) \
                 : "r"(a0), "r"(a1), "r"(a2), "r"(a3), "r"(b0), "r"(b1))
__device__ __forceinline__ unsigned smem_u32(const void* p) {
    return (unsigned)__cvta_generic_to_shared(p);
}

// ---------------- static scratch (no cudaMalloc allowed) -----------------------
__device__ __half g_xh_h[N_NODES * HC];     // fp16 messages (L2-resident)
__device__ float  g_as [N_NODES * NH];
__device__ float  g_ad [N_NODES * NH];
__device__ __half g_out_h[N_PAD * HC];      // fp16 aggregated messages (pad rows = 0)
__device__ int    g_off[N_NODES + 1];
__device__ int    g_cur[N_NODES];
__device__ int    g_srcl[ET];               // CSR-by-dst: src node per slot
// fp16 col-major ("B") weights for mma: row j = contiguous K column
__device__ __align__(16) __half g_W1h[NL * DFF * HC];  // [l][j][k]
__device__ __align__(16) __half g_W2h[NL * HID * DFF]; // [l][j][k]

// one-shot fp16 weight prep (launch #1; 164K threads)
__global__ void k_wprep(const float* __restrict__ W1, const float* __restrict__ W2) {
    int t = blockIdx.x * blockDim.x + threadIdx.x;
    if (t < NL * DFF * HC) {
        int l = t / (DFF * HC), r = t % (DFF * HC);
        int j = r / HC, k = r % HC;
        g_W1h[t] = __float2half_rn(W1[(size_t)l * HC * DFF + k * DFF + j]);
    }
    int u = t - NL * DFF * HC;
    if (u >= 0 && u < NL * HID * DFF) {
        int l = u / (HID * DFF), r = u % (HID * DFF);
        int j = r / DFF, k = r % DFF;
        g_W2h[u] = __float2half_rn(W2[(size_t)l * DFF * HID + k * HID + j]);
    }
}

// ================= CSR construction (graph is layer-invariant) =================
__global__ void k_csr_init() {
    int i = blockIdx.x * blockDim.x + threadIdx.x;
    if (i < N_NODES) g_cur[i] = 1;       // self loop pre-counted
}

__global__ void k_csr_count(const int* __restrict__ ei) {
    int e = blockIdx.x * blockDim.x + threadIdx.x;
    if (e < E_EDGES) atomicAdd(&g_cur[ei[E_EDGES + e]], 1);
}

__global__ void k_csr_scan() {
    __shared__ int ps[1024];
    const int CH = 20;
    int t = threadIdx.x;
    int base = t * CH;
    int mysum = 0;
    for (int i = 0; i < CH; i++) { int idx = base + i; if (idx < N_NODES) mysum += g_cur[idx]; }
    ps[t] = mysum;
    __syncthreads();
    for (int d = 1; d < 1024; d <<= 1) {
        int v = (t >= d) ? ps[t - d] : 0;
        __syncthreads();
        ps[t] += v;
        __syncthreads();
    }
    int run = ps[t] - mysum;
    for (int i = 0; i < CH; i++) {
        int idx = base + i;
        if (idx < N_NODES) { int deg = g_cur[idx]; g_off[idx] = run; g_cur[idx] = run; run += deg; }
    }
    if (t == 1023) g_off[N_NODES] = ps[1023];
}

__global__ void k_csr_fill(const int* __restrict__ ei) {
    int e = blockIdx.x * blockDim.x + threadIdx.x;
    if (e >= ET) return;
    int src, dst;
    if (e < E_EDGES) { src = ei[e]; dst = ei[E_EDGES + e]; }
    else             { src = dst = e - E_EDGES; }
    int pos = atomicAdd(&g_cur[dst], 1);
    g_srcl[pos] = src;
}

// ====== scalar dense kernels (R9 form: coalesced row-major weight loads) =======

// h = (x @ We + be) * 8.  block 256; 16 nodes.  thread = (ch j, j+32) x 2 nodes
__global__ void __launch_bounds__(256, 4)
k_embed(const float* __restrict__ x, const float* __restrict__ We,
        const float* __restrict__ be, float* __restrict__ h) {
    int t = threadIdx.x;
    int jp = t & 31, g = t >> 5;               // g 0..7 -> nodes g*2, g*2+1
    int n0 = blockIdx.x * 16;
    __shared__ __align__(16) float4 xs[16 * 64];   // 16 KB
#pragma unroll
    for (int q = 0; q < 4; q++) {
        int fi = t + q * 256;
        int row = fi >> 6, c4 = fi & 63;
        xs[fi] = *(const float4*)(x + (size_t)(n0 + row) * IN_DIM + c4 * 4);
    }
    __syncthreads();
    u64t accA[2] = {0ULL, 0ULL}, accB[2] = {0ULL, 0ULL};
#pragma unroll 1
    for (int kc = 0; kc < 32; kc++) {          // K=256 in chunks of 8
        u64t wpA[4], wpB[4];
#pragma unroll
        for (int m = 0; m < 4; m++) {
            wpA[m] = pk2(We[(size_t)(kc * 8 + 2 * m) * HID + jp],
                         We[(size_t)(kc * 8 + 2 * m + 1) * HID + jp]);
            wpB[m] = pk2(We[(size_t)(kc * 8 + 2 * m) * HID + jp + 32],
                         We[(size_t)(kc * 8 + 2 * m + 1) * HID + jp + 32]);
        }
#pragma unroll
        for (int k4 = 0; k4 < 2; k4++) {
#pragma unroll
            for (int n = 0; n < 2; n++) {
                ulonglong2 v = ((const ulonglong2*)xs)[(g * 2 + n) * 64 + kc * 2 + k4];
                FMA2(accA[n], wpA[2 * k4],     v.x);
                FMA2(accA[n], wpA[2 * k4 + 1], v.y);
                FMA2(accB[n], wpB[2 * k4],     v.x);
                FMA2(accB[n], wpB[2 * k4 + 1], v.y);
            }
        }
    }
    float bA = be[jp], bB = be[jp + 32];
#pragma unroll
    for (int n = 0; n < 2; n++) {
        float2 fa = upk2(accA[n]), fb = upk2(accB[n]);
        h[(size_t)(n0 + g * 2 + n) * HID + jp]      = (fa.x + fa.y + bA) * 8.0f;
        h[(size_t)(n0 + g * 2 + n) * HID + jp + 32] = (fb.x + fb.y + bB) * 8.0f;
    }
}

// xh = h @ Wc (fp16) + a_s/a_d.  block 256; 32 nodes/block.
__global__ void __launch_bounds__(256, 2)
k_xh_att(const float* __restrict__ h, const float* __restrict__ Wc,
         const float* __restrict__ att_src, const float* __restrict__ att_dst) {
    int t = threadIdx.x;
    int jp = t & 127, ng = t >> 7;             // channels jp, jp+128; nodes ng*16..+16
    int w = t >> 5, lane = t & 31;
    int n0 = blockIdx.x * 32;
    __shared__ __align__(16) float4 xs[32 * 16];   // 8 KB
    __shared__ float spA[8][16], dpA[8][16], spB[8][16], dpB[8][16];
#pragma unroll
    for (int q = 0; q < 2; q++) {
        int fi = t + q * 256;
        int row = fi >> 4, c4 = fi & 15;
        xs[fi] = *(const float4*)(h + (size_t)(n0 + row) * HID + c4 * 4);
    }
    __syncthreads();
    u64t accA[16], accB[16];
#pragma unroll
    for (int n = 0; n < 16; n++) { accA[n] = 0ULL; accB[n] = 0ULL; }
#pragma unroll 1
    for (int kc = 0; kc < 8; kc++) {           // K=64 in chunks of 8
        u64t wpA[4], wpB[4];
#pragma unroll
        for (int m = 0; m < 4; m++) {
            wpA[m] = pk2(Wc[(size_t)(kc * 8 + 2 * m) * HC + jp],
                         Wc[(size_t)(kc * 8 + 2 * m + 1) * HC + jp]);
            wpB[m] = pk2(Wc[(size_t)(kc * 8 + 2 * m) * HC + jp + 128],
                         Wc[(size_t)(kc * 8 + 2 * m + 1) * HC + jp + 128]);
        }
#pragma unroll
        for (int k4 = 0; k4 < 2; k4++) {
#pragma unroll
            for (int n = 0; n < 16; n++) {
                ulonglong2 v = ((const ulonglong2*)xs)[(ng * 16 + n) * 16 + kc * 2 + k4];
                FMA2(accA[n], wpA[2 * k4],     v.x);
                FMA2(accA[n], wpA[2 * k4 + 1], v.y);
                FMA2(accB[n], wpB[2 * k4],     v.x);
                FMA2(accB[n], wpB[2 * k4 + 1], v.y);
            }
        }
    }
    float asA = att_src[jp], adA = att_dst[jp];
    float asB = att_src[jp + 128], adB = att_dst[jp + 128];
#pragma unroll
    for (int n = 0; n < 16; n++) {
        float2 fa = upk2(accA[n]), fb = upk2(accB[n]);
        float vA = fa.x + fa.y, vB = fb.x + fb.y;
        int node = n0 + ng * 16 + n;
        g_xh_h[(size_t)node * HC + jp]       = __float2half_rn(vA);
        g_xh_h[(size_t)node * HC + jp + 128] = __float2half_rn(vB);
        float sA = vA * asA, dA = vA * adA, sB = vB * asB, dB = vB * adB;
#pragma unroll
        for (int o = 16; o; o >>= 1) {
            sA += __shfl_xor_sync(0xffffffffu, sA, o);
            dA += __shfl_xor_sync(0xffffffffu, dA, o);
            sB += __shfl_xor_sync(0xffffffffu, sB, o);
            dB += __shfl_xor_sync(0xffffffffu, dB, o);
        }
        if (lane == 0) { spA[w][n] = sA; dpA[w][n] = dA; spB[w][n] = sB; dpB[w][n] = dB; }
    }
    __syncthreads();
    if (t < 128) {
        int node = t >> 2, hh = t & 3;         // local node 0..31, head 0..3
        int ngg = node >> 4, nn = node & 15;
        float s, d;
        if (hh < 2) {
            int wb = ngg * 4 + hh * 2;
            s = spA[wb][nn] + spA[wb + 1][nn];
            d = dpA[wb][nn] + dpA[wb + 1][nn];
        } else {
            int wb = ngg * 4 + (hh - 2) * 2;
            s = spB[wb][nn] + spB[wb + 1][nn];
            d = dpB[wb][nn] + dpB[wb + 1][nn];
        }
        g_as[(size_t)(n0 + node) * NH + hh] = s;
        g_ad[(size_t)(n0 + node) * NH + hh] = d;
    }
}

// GAT aggregation: one warp per dst node, online softmax, unroll-4; fp16 output.
#define GAT_EDGE(Q, V) do {                                                       \
    float e = (Q) + ad; e = e > 0.f ? e : 0.2f * e;                               \
    if (e > m) {                                                                  \
        float corr = __expf(m - e);                                               \
        m = e; z *= corr;                                                         \
        a0 *= corr; a1 *= corr; a2 *= corr; a3 *= corr;                           \
        a4 *= corr; a5 *= corr; a6 *= corr; a7 *= corr;                           \
    }                                                                             \
    float wg = __expf(e - m);                                                     \
    z += wg;                                                                      \
    const __half2* hp = (const __half2*)&(V);                                     \
    float2 f0 = __half22float2(hp[0]), f1 = __half22float2(hp[1]);                \
    float2 f2 = __half22float2(hp[2]), f3 = __half22float2(hp[3]);                \
    a0 = fmaf(wg, f0.x, a0); a1 = fmaf(wg, f0.y, a1);                             \
    a2 = fmaf(wg, f1.x, a2); a3 = fmaf(wg, f1.y, a3);                             \
    a4 = fmaf(wg, f2.x, a4); a5 = fmaf(wg, f2.y, a5);                             \
    a6 = fmaf(wg, f3.x, a6); a7 = fmaf(wg, f3.y, a7);                             \
} while (0)

__global__ void k_gat(const float* __restrict__ bc) {
    int w = (blockIdx.x * blockDim.x + threadIdx.x) >> 5;
    if (w >= N_NODES) return;
    int lane = threadIdx.x & 31;
    int hh = lane >> 3;                  // head owning channels [lane*8, lane*8+8)
    int beg = g_off[w], end = g_off[w + 1];
    float ad = g_ad[w * NH + hh];
    float m = -INFINITY, z = 0.f;
    float a0 = 0, a1 = 0, a2 = 0, a3 = 0, a4 = 0, a5 = 0, a6 = 0, a7 = 0;
    int p = beg;
    for (; p + 4 <= end; p += 4) {       // MLP=4 front-batched
        int s0 = g_srcl[p], s1 = g_srcl[p + 1], s2 = g_srcl[p + 2], s3 = g_srcl[p + 3];
        float q0 = g_as[s0 * NH + hh];
        float q1 = g_as[s1 * NH + hh];
        float q2 = g_as[s2 * NH + hh];
        float q3 = g_as[s3 * NH + hh];
        uint4 v0 = *(const uint4*)(g_xh_h + (size_t)s0 * HC + lane * 8);
        uint4 v1 = *(const uint4*)(g_xh_h + (size_t)s1 * HC + lane * 8);
        uint4 v2 = *(const uint4*)(g_xh_h + (size_t)s2 * HC + lane * 8);
        uint4 v3 = *(const uint4*)(g_xh_h + (size_t)s3 * HC + lane * 8);
        GAT_EDGE(q0, v0);
        GAT_EDGE(q1, v1);
        GAT_EDGE(q2, v2);
        GAT_EDGE(q3, v3);
    }
    for (; p < end; p++) {
        int s0 = g_srcl[p];
        float q0 = g_as[s0 * NH + hh];
        uint4 v0 = *(const uint4*)(g_xh_h + (size_t)s0 * HC + lane * 8);
        GAT_EDGE(q0, v0);
    }
    float inv = 1.f / (z + 1e-16f);
    const float4* bcv = (const float4*)(bc + lane * 8);
    float4 c0 = bcv[0], c1 = bcv[1];
    __half2 q[4];
    q[0] = __floats2half2_rn(fmaf(a0, inv, c0.x), fmaf(a1, inv, c0.y));
    q[1] = __floats2half2_rn(fmaf(a2, inv, c0.z), fmaf(a3, inv, c0.w));
    q[2] = __floats2half2_rn(fmaf(a4, inv, c1.x), fmaf(a5, inv, c1.y));
    q[3] = __floats2half2_rn(fmaf(a6, inv, c1.z), fmaf(a7, inv, c1.w));
    *(uint4*)(g_out_h + (size_t)w * HC + lane * 8) = *(uint4*)q;
}

// ====== fused FFN via tensor cores (mma.sync fp16 -> fp32) =====================
// 64 nodes/block, 256 thr (8 warps). Stage A: [64x256]@[256x128]; gelu;
// Stage B: [64x128]@[128x64]; LayerNorm fp32; h += LN(f).
#define SRA 264   // smem halves stride for X   (264*2B: rows shift 4 banks)
#define SFB 136   // smem halves stride for ff  (136*2B: rows shift 4 banks)
__global__ void __launch_bounds__(256, 2)
k_ffn(int l, const float* __restrict__ b1, const float* __restrict__ b2,
      const float* __restrict__ lng, const float* __restrict__ lnb,
      float* __restrict__ h) {
    int t = threadIdx.x, lane = t & 31, w = t >> 5;
    int n0 = blockIdx.x * 64;
    __shared__ __align__(16) __half pool_h[64 * SRA];  // 33 KB, staged
    __shared__ float2 stats[64];
    // phase 1: load X tile (64 x 256 halves) from g_out_h
    for (int i = t; i < 64 * 32; i += 256) {
        int row = i >> 5, c8 = i & 31;
        *(uint4*)(pool_h + row * SRA + c8 * 8) =
            *(const uint4*)(g_out_h + (size_t)(n0 + row) * HC + c8 * 8);
    }
    __syncthreads();
    // stage A: warp w -> m-tile (w&3)*16, n-stripe (w>>2)*64 (8 n-tiles of 8)
    int g = lane >> 2, c = lane & 3;
    int m0 = (w & 3) * 16;
    int nsA = (w >> 2) * 64;
    unsigned xbase = smem_u32(pool_h);
    int rowA = m0 + (lane & 7) + ((lane >> 3) & 1) * 8;
    int colA = ((lane >> 4) & 1) * 8;
    float acc[8][4];
#pragma unroll
    for (int nt = 0; nt < 8; nt++)
#pragma unroll
        for (int i = 0; i < 4; i++) acc[nt][i] = 0.f;
    const __half* W1h = g_W1h + (size_t)l * DFF * HC;
#pragma unroll 1
    for (int kt = 0; kt < 16; kt++) {
        unsigned a0, a1, a2, a3;
        LDSM4(a0, a1, a2, a3, xbase + (unsigned)(rowA * SRA + kt * 16 + colA) * 2u);
#pragma unroll
        for (int nt = 0; nt < 8; nt++) {
            const __half* bp = W1h + (size_t)(nsA + nt * 8 + g) * HC + kt * 16 + 2 * c;
            unsigned b0 = *(const unsigned*)bp;
            unsigned b1r = *(const unsigned*)(bp + 8);
            MMA16816(acc[nt], a0, a1, a2, a3, b0, b1r);
        }
    }
    __syncthreads();                     // all X reads done; reuse pool for ff
    // gelu + store fp16 ff tile (stride SFB)
    __half* ff = pool_h;
#pragma unroll
    for (int nt = 0; nt < 8; nt++) {
        int col = nsA + nt * 8 + 2 * c;
        float bA = b1[col], bB = b1[col + 1];
        float v0 = acc[nt][0] + bA, v1 = acc[nt][1] + bB;
        float v2 = acc[nt][2] + bA, v3 = acc[nt][3] + bB;
        float g0 = 0.5f * v0 * (1.0f + erff(v0 * 0.70710678118654752f));
        float g1 = 0.5f * v1 * (1.0f + erff(v1 * 0.70710678118654752f));
        float g2 = 0.5f * v2 * (1.0f + erff(v2 * 0.70710678118654752f));
        float g3 = 0.5f * v3 * (1.0f + erff(v3 * 0.70710678118654752f));
        *(__half2*)(ff + (m0 + g) * SFB + col)     = __floats2half2_rn(g0, g1);
        *(__half2*)(ff + (m0 + 8 + g) * SFB + col) = __floats2half2_rn(g2, g3);
    }
    __syncthreads();
    // stage B: warp w -> m-tile (w&3)*16, n-stripe (w>>2)*32 (4 n-tiles of 8)
    int nsB = (w >> 2) * 32;
    int rowB = m0 + (lane & 7) + ((lane >> 3) & 1) * 8;
    int colB = ((lane >> 4) & 1) * 8;
    float acc2[4][4];
#pragma unroll
    for (int nt = 0; nt < 4; nt++)
#pragma unroll
        for (int i = 0; i < 4; i++) acc2[nt][i] = 0.f;
    const __half* W2h = g_W2h + (size_t)l * HID * DFF;
#pragma unroll 1
    for (int kt = 0; kt < 8; kt++) {
        unsigned a0, a1, a2, a3;
        LDSM4(a0, a1, a2, a3, xbase + (unsigned)(rowB * SFB + kt * 16 + colB) * 2u);
#pragma unroll
        for (int nt = 0; nt < 4; nt++) {
            const __half* bp = W2h + (size_t)(nsB + nt * 8 + g) * DFF + kt * 16 + 2 * c;
            unsigned b0 = *(const unsigned*)bp;
            unsigned b1r = *(const unsigned*)(bp + 8);
            MMA16816(acc2[nt], a0, a1, a2, a3, b0, b1r);
        }
    }
    __syncthreads();                     // all ff reads done; reuse pool for LN stash
    float* sln = (float*)pool_h;         // 64 x 65 f32 (16.6 KB)
#pragma unroll
    for (int nt = 0; nt < 4; nt++) {
        int col = nsB + nt * 8 + 2 * c;
        float bA = b2[col], bB = b2[col + 1];
        sln[(m0 + g) * 65 + col]         = acc2[nt][0] + bA;
        sln[(m0 + g) * 65 + col + 1]     = acc2[nt][1] + bB;
        sln[(m0 + 8 + g) * 65 + col]     = acc2[nt][2] + bA;
        sln[(m0 + 8 + g) * 65 + col + 1] = acc2[nt][3] + bB;
    }
    __syncthreads();
    // LayerNorm: 4 threads per node, each sums 16
    int node = t >> 2, part = t & 3;
    float s = 0.f, sq = 0.f;
#pragma unroll
    for (int k = 0; k < 16; k++) {
        float v = sln[node * 65 + part * 16 + k];
        s += v; sq = fmaf(v, v, sq);
    }
    s  += __shfl_xor_sync(0xffffffffu, s, 1);  s  += __shfl_xor_sync(0xffffffffu, s, 2);
    sq += __shfl_xor_sync(0xffffffffu, sq, 1); sq += __shfl_xor_sync(0xffffffffu, sq, 2);
    if (part == 0) {
        float mean = s * (1.f / 64.f);
        stats[node] = make_float2(mean, sq * (1.f / 64.f) - mean * mean);
    }
    __syncthreads();
    if (n0 + node < N_NODES) {
        float2 st = stats[node];
        float rinv = rsqrtf(st.y + 1e-5f);
#pragma unroll
        for (int k = 0; k < 16; k++) {
            int col = part * 16 + k;
            float nv = (sln[node * 65 + col] - st.x) * rinv * lng[col] + lnb[col];
            h[(size_t)(n0 + node) * HID + col] += nv;
        }
    }
}

// ================= driver ======================================================
extern "C" void kernel_launch(void* const* d_in, const int* in_sizes, int n_in,
                              void* d_out, int out_size) {
    const float* x       = (const float*)d_in[0];
    const int*   ei      = (const int*)  d_in[1];
    const float* We      = (const float*)d_in[2];
    const float* be      = (const float*)d_in[3];
    const float* Wc      = (const float*)d_in[4];
    const float* att_src = (const float*)d_in[5];
    const float* att_dst = (const float*)d_in[6];
    const float* bc      = (const float*)d_in[7];
    const float* W1      = (const float*)d_in[8];
    const float* b1      = (const float*)d_in[9];
    const float* W2      = (const float*)d_in[10];
    const float* b2      = (const float*)d_in[11];
    const float* ln_g    = (const float*)d_in[12];
    const float* ln_b    = (const float*)d_in[13];

    float* h = (float*)d_out;

    // k_xh_att stays the profiled (4th) launch.
    k_wprep    <<<640, 256>>>(W1, W2);                         // 1
    k_csr_init <<<(N_NODES + 255) / 256, 256>>>();             // 2
    k_embed    <<<1250, 256>>>(x, We, be, h);                  // 3
    k_xh_att   <<<625, 256>>>(h, Wc, att_src, att_dst);        // 4 (layer 0)
    k_csr_count<<<(E_EDGES + 255) / 256, 256>>>(ei);           // 5
    k_csr_scan <<<1, 1024>>>();                                // 6
    k_csr_fill <<<(ET + 255) / 256, 256>>>(ei);                // 7
    k_gat      <<<2500, 256>>>(bc);                            // 8 (layer 0)
    k_ffn      <<<313, 256>>>(0, b1, b2, ln_g, ln_b, h);       // 9 (layer 0)

    for (int l = 1; l < NL; l++) {
        k_xh_att<<<625, 256>>>(h, Wc + (size_t)l * HID * HC,
                               att_src + l * NH * C, att_dst + l * NH * C);
        k_gat   <<<2500, 256>>>(bc + l * HC);
        k_ffn   <<<313, 256>>>(l, b1 + l * DFF, b2 + l * HID,
                               ln_g + l * HID, ln_b + l * HID, h);
    }
}

// round 12
// speedup vs baseline: 2.4284x; 1.0268x over previous
#include <cuda_runtime.h>
#include <cuda_fp16.h>
#include <math.h>

#define N_NODES 20000
#define N_PAD   20032                 // padded rows for 64-node mma tiles
#define E_EDGES 320000
#define ET      (E_EDGES + N_NODES)   // 340000
#define IN_DIM  256
#define HID     64
#define NH      4
#define C       64
#define HC      256
#define DFF     128
#define NL      4

typedef unsigned long long u64t;

// packed f32x2 helpers (FFMA2 path)
#define FMA2(d, a, b) asm("fma.rn.f32x2 %0, %1, %2, %0;" : "+l"(d) : "l"(a), "l"(b))
__device__ __forceinline__ u64t pk2(float lo, float hi) {
    u64t r; asm("mov.b64 %0, {%1, %2};" : "=l"(r) : "f"(lo), "f"(hi)); return r;
}
__device__ __forceinline__ float2 upk2(u64t v) {
    float2 f; asm("mov.b64 {%0, %1}, %2;" : "=f"(f.x), "=f"(f.y) : "l"(v)); return f;
}

// tensor-core helpers (validated in R11)
#define LDSM4(a0, a1, a2, a3, addr) \
    asm volatile("ldmatrix.sync.aligned.m8n8.x4.shared.b16 {%0,%1,%2,%3}, [%4];" \
                 : "=r"(a0), "=r"(a1), "=r"(a2), "=r"(a3) : "r"(addr))
#define MMA16816(cc, a0, a1, a2, a3, b0, b1) \
    asm volatile("mma.sync.aligned.m16n8k16.row.col.f32.f16.f16.f32 " \
                 "{%0,%1,%2,%3}, {%4,%5,%6,%7}, {%8,%9}, {%0,%1,%2,%3};" \
                 : "+f"((cc)[0]), "+f"((cc)[1]), "+f"((cc)[2]), "+f"((cc)[3]) \
                 : "r"(a0), "r"(a1), "r"(a2), "r"(a3), "r"(b0), "r"(b1))
__device__ __forceinline__ unsigned smem_u32(const void* p) {
    return (unsigned)__cvta_generic_to_shared(p);
}

// ---------------- static scratch (no cudaMalloc allowed) -----------------------
__device__ __half g_xh_h[N_NODES * HC];     // fp16 messages (L2-resident)
__device__ float  g_as [N_NODES * NH];
__device__ float  g_ad [N_NODES * NH];
__device__ __half g_out_h[N_PAD * HC];      // fp16 aggregated messages (pad rows = 0)
__device__ int    g_off[N_NODES + 1];
__device__ int    g_cur[N_NODES];
__device__ int    g_srcl[ET];               // CSR-by-dst: src node per slot
// fp16 col-major ("B") weights for mma: row j = contiguous K column
__device__ __align__(16) __half g_W1h[NL * DFF * HC];  // [l][j][k]
__device__ __align__(16) __half g_W2h[NL * HID * DFF]; // [l][j][k]
__device__ __align__(16) __half g_Wch[NL * HC * HID];  // [l][j][k]

#define SZ_W1 (NL * DFF * HC)   // 131072
#define SZ_W2 (NL * HID * DFF)  // 32768
#define SZ_WC (NL * HC * HID)   // 65536

// one-shot fp16 weight prep (launch #1; 229K threads)
__global__ void k_wprep(const float* __restrict__ W1, const float* __restrict__ W2,
                        const float* __restrict__ Wc) {
    int t = blockIdx.x * blockDim.x + threadIdx.x;
    if (t < SZ_W1) {
        int l = t / (DFF * HC), r = t % (DFF * HC);
        int j = r / HC, k = r % HC;
        g_W1h[t] = __float2half_rn(W1[(size_t)l * HC * DFF + k * DFF + j]);
    }
    int u = t - SZ_W1;
    if (u >= 0 && u < SZ_W2) {
        int l = u / (HID * DFF), r = u % (HID * DFF);
        int j = r / DFF, k = r % DFF;
        g_W2h[u] = __float2half_rn(W2[(size_t)l * DFF * HID + k * HID + j]);
    }
    int v = u - SZ_W2;
    if (v >= 0 && v < SZ_WC) {
        int l = v / (HC * HID), r = v % (HC * HID);
        int j = r / HID, k = r % HID;
        g_Wch[v] = __float2half_rn(Wc[(size_t)l * HID * HC + k * HC + j]);
    }
}

// ================= CSR construction (graph is layer-invariant) =================
__global__ void k_csr_init() {
    int i = blockIdx.x * blockDim.x + threadIdx.x;
    if (i < N_NODES) g_cur[i] = 1;       // self loop pre-counted
}

__global__ void k_csr_count(const int* __restrict__ ei) {
    int e = blockIdx.x * blockDim.x + threadIdx.x;
    if (e < E_EDGES) atomicAdd(&g_cur[ei[E_EDGES + e]], 1);
}

__global__ void k_csr_scan() {
    __shared__ int ps[1024];
    const int CH = 20;
    int t = threadIdx.x;
    int base = t * CH;
    int mysum = 0;
    for (int i = 0; i < CH; i++) { int idx = base + i; if (idx < N_NODES) mysum += g_cur[idx]; }
    ps[t] = mysum;
    __syncthreads();
    for (int d = 1; d < 1024; d <<= 1) {
        int v = (t >= d) ? ps[t - d] : 0;
        __syncthreads();
        ps[t] += v;
        __syncthreads();
    }
    int run = ps[t] - mysum;
    for (int i = 0; i < CH; i++) {
        int idx = base + i;
        if (idx < N_NODES) { int deg = g_cur[idx]; g_off[idx] = run; g_cur[idx] = run; run += deg; }
    }
    if (t == 1023) g_off[N_NODES] = ps[1023];
}

__global__ void k_csr_fill(const int* __restrict__ ei) {
    int e = blockIdx.x * blockDim.x + threadIdx.x;
    if (e >= ET) return;
    int src, dst;
    if (e < E_EDGES) { src = ei[e]; dst = ei[E_EDGES + e]; }
    else             { src = dst = e - E_EDGES; }
    int pos = atomicAdd(&g_cur[dst], 1);
    g_srcl[pos] = src;
}

// ====== embed (scalar FFMA2, R9 form) ==========================================
__global__ void __launch_bounds__(256, 4)
k_embed(const float* __restrict__ x, const float* __restrict__ We,
        const float* __restrict__ be, float* __restrict__ h) {
    int t = threadIdx.x;
    int jp = t & 31, g = t >> 5;               // g 0..7 -> nodes g*2, g*2+1
    int n0 = blockIdx.x * 16;
    __shared__ __align__(16) float4 xs[16 * 64];   // 16 KB
#pragma unroll
    for (int q = 0; q < 4; q++) {
        int fi = t + q * 256;
        int row = fi >> 6, c4 = fi & 63;
        xs[fi] = *(const float4*)(x + (size_t)(n0 + row) * IN_DIM + c4 * 4);
    }
    __syncthreads();
    u64t accA[2] = {0ULL, 0ULL}, accB[2] = {0ULL, 0ULL};
#pragma unroll 1
    for (int kc = 0; kc < 32; kc++) {          // K=256 in chunks of 8
        u64t wpA[4], wpB[4];
#pragma unroll
        for (int m = 0; m < 4; m++) {
            wpA[m] = pk2(We[(size_t)(kc * 8 + 2 * m) * HID + jp],
                         We[(size_t)(kc * 8 + 2 * m + 1) * HID + jp]);
            wpB[m] = pk2(We[(size_t)(kc * 8 + 2 * m) * HID + jp + 32],
                         We[(size_t)(kc * 8 + 2 * m + 1) * HID + jp + 32]);
        }
#pragma unroll
        for (int k4 = 0; k4 < 2; k4++) {
#pragma unroll
            for (int n = 0; n < 2; n++) {
                ulonglong2 v = ((const ulonglong2*)xs)[(g * 2 + n) * 64 + kc * 2 + k4];
                FMA2(accA[n], wpA[2 * k4],     v.x);
                FMA2(accA[n], wpA[2 * k4 + 1], v.y);
                FMA2(accB[n], wpB[2 * k4],     v.x);
                FMA2(accB[n], wpB[2 * k4 + 1], v.y);
            }
        }
    }
    float bA = be[jp], bB = be[jp + 32];
#pragma unroll
    for (int n = 0; n < 2; n++) {
        float2 fa = upk2(accA[n]), fb = upk2(accB[n]);
        h[(size_t)(n0 + g * 2 + n) * HID + jp]      = (fa.x + fa.y + bA) * 8.0f;
        h[(size_t)(n0 + g * 2 + n) * HID + jp + 32] = (fb.x + fb.y + bB) * 8.0f;
    }
}

// ====== xh = h @ Wc + attention, via tensor cores ==============================
// 64 nodes/block, 8 warps: warp = m-tile (w&3)*16 x n-stripe (w>>2)*128 (2 heads).
#define SXA 72    // A tile stride (halves): conflict-free ldmatrix
#define SXH 264   // xh staging stride (halves): conflict-free epilogue
__global__ void __launch_bounds__(256, 2)
k_xh_att(const float* __restrict__ h, int l,
         const float* __restrict__ att_src, const float* __restrict__ att_dst) {
    int t = threadIdx.x, lane = t & 31, w = t >> 5;
    int n0 = blockIdx.x * 64;
    __shared__ __align__(16) __half pool[64 * SXH];   // 33.8 KB (A tile, then xh tile)
    __shared__ float sAs[HC], sAd[HC];
    if (t < HC) { sAs[t] = att_src[t]; sAd[t] = att_dst[t]; }
    // A tile: h fp32 -> fp16 [64 x 64], stride SXA, OOB rows zero
    for (int i = t; i < 64 * 16; i += 256) {
        int row = i >> 4, c4 = i & 15;
        float4 v = make_float4(0.f, 0.f, 0.f, 0.f);
        if (n0 + row < N_NODES) v = *(const float4*)(h + (size_t)(n0 + row) * HID + c4 * 4);
        __half2* dst = (__half2*)(pool + row * SXA + c4 * 4);
        dst[0] = __floats2half2_rn(v.x, v.y);
        dst[1] = __floats2half2_rn(v.z, v.w);
    }
    __syncthreads();
    int g = lane >> 2, c = lane & 3;
    int m0 = (w & 3) * 16, ns = (w >> 2) * 128;
    unsigned abase = smem_u32(pool);
    int rowA = m0 + (lane & 7) + ((lane >> 3) & 1) * 8;
    int colA = ((lane >> 4) & 1) * 8;
    float acc[16][4];
#pragma unroll
    for (int nt = 0; nt < 16; nt++)
#pragma unroll
        for (int i = 0; i < 4; i++) acc[nt][i] = 0.f;
    const __half* Wch = g_Wch + (size_t)l * HC * HID;
#pragma unroll
    for (int kt = 0; kt < 4; kt++) {           // K=64
        unsigned a0, a1, a2, a3;
        LDSM4(a0, a1, a2, a3, abase + (unsigned)(rowA * SXA + kt * 16 + colA) * 2u);
#pragma unroll
        for (int nt = 0; nt < 16; nt++) {
            const __half* bp = Wch + (size_t)(ns + nt * 8 + g) * HID + kt * 16 + 2 * c;
            unsigned b0  = *(const unsigned*)bp;
            unsigned b1r = *(const unsigned*)(bp + 8);
            MMA16816(acc[nt], a0, a1, a2, a3, b0, b1r);
        }
    }
    __syncthreads();                           // A reads done; reuse pool for xh tile
#pragma unroll
    for (int nt = 0; nt < 16; nt++) {
        int col = ns + nt * 8 + 2 * c;
        *(__half2*)(pool + (m0 + g) * SXH + col)     = __floats2half2_rn(acc[nt][0], acc[nt][1]);
        *(__half2*)(pool + (m0 + 8 + g) * SXH + col) = __floats2half2_rn(acc[nt][2], acc[nt][3]);
    }
    __syncthreads();
    // vectorized xh store
    for (int i = t; i < 64 * 32; i += 256) {
        int row = i >> 5, c8 = i & 31;
        if (n0 + row < N_NODES)
            *(uint4*)(g_xh_h + (size_t)(n0 + row) * HC + c8 * 8) =
                *(const uint4*)(pool + row * SXH + c8 * 8);
    }
    // a_s/a_d: one thread per (node, head)
    {
        int node = t >> 2, hh = t & 3;
        const __half* rowp = pool + node * SXH + hh * 64;
        float s = 0.f, d = 0.f;
#pragma unroll
        for (int q = 0; q < 8; q++) {
            uint4 v = *(const uint4*)(rowp + q * 8);
            const __half2* hp = (const __half2*)&v;
#pragma unroll
            for (int u = 0; u < 4; u++) {
                float2 f = __half22float2(hp[u]);
                int col = hh * 64 + q * 8 + u * 2;
                s = fmaf(f.x, sAs[col], s); s = fmaf(f.y, sAs[col + 1], s);
                d = fmaf(f.x, sAd[col], d); d = fmaf(f.y, sAd[col + 1], d);
            }
        }
        if (n0 + node < N_NODES) {
            g_as[(size_t)(n0 + node) * NH + hh] = s;
            g_ad[(size_t)(n0 + node) * NH + hh] = d;
        }
    }
}

// GAT aggregation: one warp per dst node, online softmax, unroll-4; fp16 output.
#define GAT_EDGE(Q, V) do {                                                       \
    float e = (Q) + ad; e = e > 0.f ? e : 0.2f * e;                               \
    if (e > m) {                                                                  \
        float corr = __expf(m - e);                                               \
        m = e; z *= corr;                                                         \
        a0 *= corr; a1 *= corr; a2 *= corr; a3 *= corr;                           \
        a4 *= corr; a5 *= corr; a6 *= corr; a7 *= corr;                           \
    }                                                                             \
    float wg = __expf(e - m);                                                     \
    z += wg;                                                                      \
    const __half2* hp = (const __half2*)&(V);                                     \
    float2 f0 = __half22float2(hp[0]), f1 = __half22float2(hp[1]);                \
    float2 f2 = __half22float2(hp[2]), f3 = __half22float2(hp[3]);                \
    a0 = fmaf(wg, f0.x, a0); a1 = fmaf(wg, f0.y, a1);                             \
    a2 = fmaf(wg, f1.x, a2); a3 = fmaf(wg, f1.y, a3);                             \
    a4 = fmaf(wg, f2.x, a4); a5 = fmaf(wg, f2.y, a5);                             \
    a6 = fmaf(wg, f3.x, a6); a7 = fmaf(wg, f3.y, a7);                             \
} while (0)

__global__ void k_gat(const float* __restrict__ bc) {
    int w = (blockIdx.x * blockDim.x + threadIdx.x) >> 5;
    if (w >= N_NODES) return;
    int lane = threadIdx.x & 31;
    int hh = lane >> 3;                  // head owning channels [lane*8, lane*8+8)
    int beg = g_off[w], end = g_off[w + 1];
    float ad = g_ad[w * NH + hh];
    float m = -INFINITY, z = 0.f;
    float a0 = 0, a1 = 0, a2 = 0, a3 = 0, a4 = 0, a5 = 0, a6 = 0, a7 = 0;
    int p = beg;
    for (; p + 4 <= end; p += 4) {       // MLP=4 front-batched
        int s0 = g_srcl[p], s1 = g_srcl[p + 1], s2 = g_srcl[p + 2], s3 = g_srcl[p + 3];
        float q0 = g_as[s0 * NH + hh];
        float q1 = g_as[s1 * NH + hh];
        float q2 = g_as[s2 * NH + hh];
        float q3 = g_as[s3 * NH + hh];
        uint4 v0 = *(const uint4*)(g_xh_h + (size_t)s0 * HC + lane * 8);
        uint4 v1 = *(const uint4*)(g_xh_h + (size_t)s1 * HC + lane * 8);
        uint4 v2 = *(const uint4*)(g_xh_h + (size_t)s2 * HC + lane * 8);
        uint4 v3 = *(const uint4*)(g_xh_h + (size_t)s3 * HC + lane * 8);
        GAT_EDGE(q0, v0);
        GAT_EDGE(q1, v1);
        GAT_EDGE(q2, v2);
        GAT_EDGE(q3, v3);
    }
    for (; p < end; p++) {
        int s0 = g_srcl[p];
        float q0 = g_as[s0 * NH + hh];
        uint4 v0 = *(const uint4*)(g_xh_h + (size_t)s0 * HC + lane * 8);
        GAT_EDGE(q0, v0);
    }
    float inv = 1.f / (z + 1e-16f);
    const float4* bcv = (const float4*)(bc + lane * 8);
    float4 c0 = bcv[0], c1 = bcv[1];
    __half2 q[4];
    q[0] = __floats2half2_rn(fmaf(a0, inv, c0.x), fmaf(a1, inv, c0.y));
    q[1] = __floats2half2_rn(fmaf(a2, inv, c0.z), fmaf(a3, inv, c0.w));
    q[2] = __floats2half2_rn(fmaf(a4, inv, c1.x), fmaf(a5, inv, c1.y));
    q[3] = __floats2half2_rn(fmaf(a6, inv, c1.z), fmaf(a7, inv, c1.w));
    *(uint4*)(g_out_h + (size_t)w * HC + lane * 8) = *(uint4*)q;
}

// ====== fused FFN via tensor cores (validated R11) =============================
#define SRA 264   // smem halves stride for X
#define SFB 136   // smem halves stride for ff
__global__ void __launch_bounds__(256, 2)
k_ffn(int l, const float* __restrict__ b1, const float* __restrict__ b2,
      const float* __restrict__ lng, const float* __restrict__ lnb,
      float* __restrict__ h) {
    int t = threadIdx.x, lane = t & 31, w = t >> 5;
    int n0 = blockIdx.x * 64;
    __shared__ __align__(16) __half pool_h[64 * SRA];  // 33 KB, staged
    __shared__ float2 stats[64];
    for (int i = t; i < 64 * 32; i += 256) {
        int row = i >> 5, c8 = i & 31;
        *(uint4*)(pool_h + row * SRA + c8 * 8) =
            *(const uint4*)(g_out_h + (size_t)(n0 + row) * HC + c8 * 8);
    }
    __syncthreads();
    int g = lane >> 2, c = lane & 3;
    int m0 = (w & 3) * 16;
    int nsA = (w >> 2) * 64;
    unsigned xbase = smem_u32(pool_h);
    int rowA = m0 + (lane & 7) + ((lane >> 3) & 1) * 8;
    int colA = ((lane >> 4) & 1) * 8;
    float acc[8][4];
#pragma unroll
    for (int nt = 0; nt < 8; nt++)
#pragma unroll
        for (int i = 0; i < 4; i++) acc[nt][i] = 0.f;
    const __half* W1h = g_W1h + (size_t)l * DFF * HC;
#pragma unroll 1
    for (int kt = 0; kt < 16; kt++) {
        unsigned a0, a1, a2, a3;
        LDSM4(a0, a1, a2, a3, xbase + (unsigned)(rowA * SRA + kt * 16 + colA) * 2u);
#pragma unroll
        for (int nt = 0; nt < 8; nt++) {
            const __half* bp = W1h + (size_t)(nsA + nt * 8 + g) * HC + kt * 16 + 2 * c;
            unsigned b0 = *(const unsigned*)bp;
            unsigned b1r = *(const unsigned*)(bp + 8);
            MMA16816(acc[nt], a0, a1, a2, a3, b0, b1r);
        }
    }
    __syncthreads();
    __half* ff = pool_h;
#pragma unroll
    for (int nt = 0; nt < 8; nt++) {
        int col = nsA + nt * 8 + 2 * c;
        float bA = b1[col], bB = b1[col + 1];
        float v0 = acc[nt][0] + bA, v1 = acc[nt][1] + bB;
        float v2 = acc[nt][2] + bA, v3 = acc[nt][3] + bB;
        float g0 = 0.5f * v0 * (1.0f + erff(v0 * 0.70710678118654752f));
        float g1 = 0.5f * v1 * (1.0f + erff(v1 * 0.70710678118654752f));
        float g2 = 0.5f * v2 * (1.0f + erff(v2 * 0.70710678118654752f));
        float g3 = 0.5f * v3 * (1.0f + erff(v3 * 0.70710678118654752f));
        *(__half2*)(ff + (m0 + g) * SFB + col)     = __floats2half2_rn(g0, g1);
        *(__half2*)(ff + (m0 + 8 + g) * SFB + col) = __floats2half2_rn(g2, g3);
    }
    __syncthreads();
    int nsB = (w >> 2) * 32;
    int rowB = m0 + (lane & 7) + ((lane >> 3) & 1) * 8;
    int colB = ((lane >> 4) & 1) * 8;
    float acc2[4][4];
#pragma unroll
    for (int nt = 0; nt < 4; nt++)
#pragma unroll
        for (int i = 0; i < 4; i++) acc2[nt][i] = 0.f;
    const __half* W2h = g_W2h + (size_t)l * HID * DFF;
#pragma unroll 1
    for (int kt = 0; kt < 8; kt++) {
        unsigned a0, a1, a2, a3;
        LDSM4(a0, a1, a2, a3, xbase + (unsigned)(rowB * SFB + kt * 16 + colB) * 2u);
#pragma unroll
        for (int nt = 0; nt < 4; nt++) {
            const __half* bp = W2h + (size_t)(nsB + nt * 8 + g) * DFF + kt * 16 + 2 * c;
            unsigned b0 = *(const unsigned*)bp;
            unsigned b1r = *(const unsigned*)(bp + 8);
            MMA16816(acc2[nt], a0, a1, a2, a3, b0, b1r);
        }
    }
    __syncthreads();
    float* sln = (float*)pool_h;         // 64 x 65 f32
#pragma unroll
    for (int nt = 0; nt < 4; nt++) {
        int col = nsB + nt * 8 + 2 * c;
        float bA = b2[col], bB = b2[col + 1];
        sln[(m0 + g) * 65 + col]         = acc2[nt][0] + bA;
        sln[(m0 + g) * 65 + col + 1]     = acc2[nt][1] + bB;
        sln[(m0 + 8 + g) * 65 + col]     = acc2[nt][2] + bA;
        sln[(m0 + 8 + g) * 65 + col + 1] = acc2[nt][3] + bB;
    }
    __syncthreads();
    int node = t >> 2, part = t & 3;
    float s = 0.f, sq = 0.f;
#pragma unroll
    for (int k = 0; k < 16; k++) {
        float v = sln[node * 65 + part * 16 + k];
        s += v; sq = fmaf(v, v, sq);
    }
    s  += __shfl_xor_sync(0xffffffffu, s, 1);  s  += __shfl_xor_sync(0xffffffffu, s, 2);
    sq += __shfl_xor_sync(0xffffffffu, sq, 1); sq += __shfl_xor_sync(0xffffffffu, sq, 2);
    if (part == 0) {
        float mean = s * (1.f / 64.f);
        stats[node] = make_float2(mean, sq * (1.f / 64.f) - mean * mean);
    }
    __syncthreads();
    if (n0 + node < N_NODES) {
        float2 st = stats[node];
        float rinv = rsqrtf(st.y + 1e-5f);
#pragma unroll
        for (int k = 0; k < 16; k++) {
            int col = part * 16 + k;
            float nv = (sln[node * 65 + col] - st.x) * rinv * lng[col] + lnb[col];
            h[(size_t)(n0 + node) * HID + col] += nv;
        }
    }
}

// ================= driver ======================================================
extern "C" void kernel_launch(void* const* d_in, const int* in_sizes, int n_in,
                              void* d_out, int out_size) {
    const float* x       = (const float*)d_in[0];
    const int*   ei      = (const int*)  d_in[1];
    const float* We      = (const float*)d_in[2];
    const float* be      = (const float*)d_in[3];
    const float* Wc      = (const float*)d_in[4];
    const float* att_src = (const float*)d_in[5];
    const float* att_dst = (const float*)d_in[6];
    const float* bc      = (const float*)d_in[7];
    const float* W1      = (const float*)d_in[8];
    const float* b1      = (const float*)d_in[9];
    const float* W2      = (const float*)d_in[10];
    const float* b2      = (const float*)d_in[11];
    const float* ln_g    = (const float*)d_in[12];
    const float* ln_b    = (const float*)d_in[13];

    float* h = (float*)d_out;

    // k_xh_att stays the profiled (4th) launch.
    k_wprep    <<<896, 256>>>(W1, W2, Wc);                     // 1
    k_csr_init <<<(N_NODES + 255) / 256, 256>>>();             // 2
    k_embed    <<<1250, 256>>>(x, We, be, h);                  // 3
    k_xh_att   <<<313, 256>>>(h, 0, att_src, att_dst);         // 4 (layer 0)
    k_csr_count<<<(E_EDGES + 255) / 256, 256>>>(ei);           // 5
    k_csr_scan <<<1, 1024>>>();                                // 6
    k_csr_fill <<<(ET + 255) / 256, 256>>>(ei);                // 7
    k_gat      <<<2500, 256>>>(bc);                            // 8 (layer 0)
    k_ffn      <<<313, 256>>>(0, b1, b2, ln_g, ln_b, h);       // 9 (layer 0)

    for (int l = 1; l < NL; l++) {
        k_xh_att<<<313, 256>>>(h, l, att_src + l * NH * C, att_dst + l * NH * C);
        k_gat   <<<2500, 256>>>(bc + l * HC);
        k_ffn   <<<313, 256>>>(l, b1 + l * DFF, b2 + l * HID,
                               ln_g + l * HID, ln_b + l * HID, h);
    }
}

// round 13
// speedup vs baseline: 2.6558x; 1.0936x over previous
#include <cuda_runtime.h>
#include <cuda_fp16.h>
#include <math.h>

#define N_NODES 20000
#define N_PAD   20032                 // padded rows for 64-node mma tiles
#define E_EDGES 320000
#define ET      (E_EDGES + N_NODES)   // 340000
#define IN_DIM  256
#define HID     64
#define NH      4
#define C       64
#define HC      256
#define DFF     128
#define NL      4

typedef unsigned long long u64t;

// packed f32x2 helpers (FFMA2 path)
#define FMA2(d, a, b) asm("fma.rn.f32x2 %0, %1, %2, %0;" : "+l"(d) : "l"(a), "l"(b))
__device__ __forceinline__ u64t pk2(float lo, float hi) {
    u64t r; asm("mov.b64 %0, {%1, %2};" : "=l"(r) : "f"(lo), "f"(hi)); return r;
}
__device__ __forceinline__ float2 upk2(u64t v) {
    float2 f; asm("mov.b64 {%0, %1}, %2;" : "=f"(f.x), "=f"(f.y) : "l"(v)); return f;
}

// tensor-core helpers (validated R11/R12)
#define LDSM4(a0, a1, a2, a3, addr) \
    asm volatile("ldmatrix.sync.aligned.m8n8.x4.shared.b16 {%0,%1,%2,%3}, [%4];" \
                 : "=r"(a0), "=r"(a1), "=r"(a2), "=r"(a3) : "r"(addr))
#define MMA16816(cc, a0, a1, a2, a3, b0, b1) \
    asm volatile("mma.sync.aligned.m16n8k16.row.col.f32.f16.f16.f32 " \
                 "{%0,%1,%2,%3}, {%4,%5,%6,%7}, {%8,%9}, {%0,%1,%2,%3};" \
                 : "+f"((cc)[0]), "+f"((cc)[1]), "+f"((cc)[2]), "+f"((cc)[3]) \
                 : "r"(a0), "r"(a1), "r"(a2), "r"(a3), "r"(b0), "r"(b1))
__device__ __forceinline__ unsigned smem_u32(const void* p) {
    return (unsigned)__cvta_generic_to_shared(p);
}

// ---------------- static scratch (no cudaMalloc allowed) -----------------------
__device__ __half g_xh_h[N_NODES * HC];     // fp16 messages (L2-resident)
__device__ float  g_as [N_NODES * NH];
__device__ float  g_ad [N_NODES * NH];
__device__ __half g_out_h[N_PAD * HC];      // fp16 aggregated messages (pad rows = 0)
__device__ int    g_off[N_NODES + 1];
__device__ int    g_cur[N_NODES];
__device__ int    g_srcl[ET];               // CSR-by-dst: src node per slot
// fp16 col-major ("B") weights for mma: row j = contiguous K column
__device__ __align__(16) __half g_W1h[NL * DFF * HC];  // [l][j][k]
__device__ __align__(16) __half g_W2h[NL * HID * DFF]; // [l][j][k]
__device__ __align__(16) __half g_Wch[NL * HC * HID];  // [l][j][k]

#define SZ_W1 (NL * DFF * HC)   // 131072
#define SZ_W2 (NL * HID * DFF)  // 32768
#define SZ_WC (NL * HC * HID)   // 65536

// one-shot fp16 weight prep (launch #1; 229K threads)
__global__ void k_wprep(const float* __restrict__ W1, const float* __restrict__ W2,
                        const float* __restrict__ Wc) {
    int t = blockIdx.x * blockDim.x + threadIdx.x;
    if (t < SZ_W1) {
        int l = t / (DFF * HC), r = t % (DFF * HC);
        int j = r / HC, k = r % HC;
        g_W1h[t] = __float2half_rn(W1[(size_t)l * HC * DFF + k * DFF + j]);
    }
    int u = t - SZ_W1;
    if (u >= 0 && u < SZ_W2) {
        int l = u / (HID * DFF), r = u % (HID * DFF);
        int j = r / DFF, k = r % DFF;
        g_W2h[u] = __float2half_rn(W2[(size_t)l * DFF * HID + k * HID + j]);
    }
    int v = u - SZ_W2;
    if (v >= 0 && v < SZ_WC) {
        int l = v / (HC * HID), r = v % (HC * HID);
        int j = r / HID, k = r % HID;
        g_Wch[v] = __float2half_rn(Wc[(size_t)l * HID * HC + k * HC + j]);
    }
}

// ================= CSR construction (graph is layer-invariant) =================
__global__ void k_csr_init() {
    int i = blockIdx.x * blockDim.x + threadIdx.x;
    if (i < N_NODES) g_cur[i] = 1;       // self loop pre-counted
}

__global__ void k_csr_count(const int* __restrict__ ei) {
    int e = blockIdx.x * blockDim.x + threadIdx.x;
    if (e < E_EDGES) atomicAdd(&g_cur[ei[E_EDGES + e]], 1);
}

__global__ void k_csr_scan() {
    __shared__ int ps[1024];
    const int CH = 20;
    int t = threadIdx.x;
    int base = t * CH;
    int mysum = 0;
    for (int i = 0; i < CH; i++) { int idx = base + i; if (idx < N_NODES) mysum += g_cur[idx]; }
    ps[t] = mysum;
    __syncthreads();
    for (int d = 1; d < 1024; d <<= 1) {
        int v = (t >= d) ? ps[t - d] : 0;
        __syncthreads();
        ps[t] += v;
        __syncthreads();
    }
    int run = ps[t] - mysum;
    for (int i = 0; i < CH; i++) {
        int idx = base + i;
        if (idx < N_NODES) { int deg = g_cur[idx]; g_off[idx] = run; g_cur[idx] = run; run += deg; }
    }
    if (t == 1023) g_off[N_NODES] = ps[1023];
}

__global__ void k_csr_fill(const int* __restrict__ ei) {
    int e = blockIdx.x * blockDim.x + threadIdx.x;
    if (e >= ET) return;
    int src, dst;
    if (e < E_EDGES) { src = ei[e]; dst = ei[E_EDGES + e]; }
    else             { src = dst = e - E_EDGES; }
    int pos = atomicAdd(&g_cur[dst], 1);
    g_srcl[pos] = src;
}

// ====== embed (scalar FFMA2, R9 form) ==========================================
__global__ void __launch_bounds__(256, 4)
k_embed(const float* __restrict__ x, const float* __restrict__ We,
        const float* __restrict__ be, float* __restrict__ h) {
    int t = threadIdx.x;
    int jp = t & 31, g = t >> 5;               // g 0..7 -> nodes g*2, g*2+1
    int n0 = blockIdx.x * 16;
    __shared__ __align__(16) float4 xs[16 * 64];   // 16 KB
#pragma unroll
    for (int q = 0; q < 4; q++) {
        int fi = t + q * 256;
        int row = fi >> 6, c4 = fi & 63;
        xs[fi] = *(const float4*)(x + (size_t)(n0 + row) * IN_DIM + c4 * 4);
    }
    __syncthreads();
    u64t accA[2] = {0ULL, 0ULL}, accB[2] = {0ULL, 0ULL};
#pragma unroll 1
    for (int kc = 0; kc < 32; kc++) {          // K=256 in chunks of 8
        u64t wpA[4], wpB[4];
#pragma unroll
        for (int m = 0; m < 4; m++) {
            wpA[m] = pk2(We[(size_t)(kc * 8 + 2 * m) * HID + jp],
                         We[(size_t)(kc * 8 + 2 * m + 1) * HID + jp]);
            wpB[m] = pk2(We[(size_t)(kc * 8 + 2 * m) * HID + jp + 32],
                         We[(size_t)(kc * 8 + 2 * m + 1) * HID + jp + 32]);
        }
#pragma unroll
        for (int k4 = 0; k4 < 2; k4++) {
#pragma unroll
            for (int n = 0; n < 2; n++) {
                ulonglong2 v = ((const ulonglong2*)xs)[(g * 2 + n) * 64 + kc * 2 + k4];
                FMA2(accA[n], wpA[2 * k4],     v.x);
                FMA2(accA[n], wpA[2 * k4 + 1], v.y);
                FMA2(accB[n], wpB[2 * k4],     v.x);
                FMA2(accB[n], wpB[2 * k4 + 1], v.y);
            }
        }
    }
    float bA = be[jp], bB = be[jp + 32];
#pragma unroll
    for (int n = 0; n < 2; n++) {
        float2 fa = upk2(accA[n]), fb = upk2(accB[n]);
        h[(size_t)(n0 + g * 2 + n) * HID + jp]      = (fa.x + fa.y + bA) * 8.0f;
        h[(size_t)(n0 + g * 2 + n) * HID + jp + 32] = (fb.x + fb.y + bB) * 8.0f;
    }
}

// ====== xh = h @ Wc + attention, tensor cores, smem-staged weights =============
// 64 nodes/block, 8 warps: warp = m-tile (w&3)*16 x n-stripe (w>>2)*128.
// smem pool: [A 64x72][Wc 256x72] during mainloop; reused as xh tile [64x264] after.
#define SXA 72    // A / W row stride (halves): 16B row rotation, conflict-free ldmatrix
#define SXH 264   // xh staging stride (halves)
#define XPOOL (64 * SXA + 256 * SXA)   // 23040 halves = 46 KB
__global__ void __launch_bounds__(256, 2)
k_xh_att(const float* __restrict__ h, int l,
         const float* __restrict__ att_src, const float* __restrict__ att_dst) {
    int t = threadIdx.x, lane = t & 31, w = t >> 5;
    int n0 = blockIdx.x * 64;
    __shared__ __align__(16) __half pool[XPOOL];
    __shared__ float sAs[HC], sAd[HC];
    __half* At = pool;                 // 64 rows x SXA
    __half* Wt = pool + 64 * SXA;      // 256 rows x SXA
    if (t < HC) { sAs[t] = att_src[t]; sAd[t] = att_dst[t]; }
    // A tile: h fp32 -> fp16 [64 x 64], OOB rows zero
    for (int i = t; i < 64 * 16; i += 256) {
        int row = i >> 4, c4 = i & 15;
        float4 v = make_float4(0.f, 0.f, 0.f, 0.f);
        if (n0 + row < N_NODES) v = *(const float4*)(h + (size_t)(n0 + row) * HID + c4 * 4);
        __half2* dst = (__half2*)(At + row * SXA + c4 * 4);
        dst[0] = __floats2half2_rn(v.x, v.y);
        dst[1] = __floats2half2_rn(v.z, v.w);
    }
    // Wc tile: 256 rows x 64 halves, coalesced uint4
    {
        const __half* Wch = g_Wch + (size_t)l * HC * HID;
        for (int i = t; i < 2048; i += 256) {
            int row = i >> 3, seg = i & 7;
            *(uint4*)(Wt + row * SXA + seg * 8) = *(const uint4*)(Wch + row * HID + seg * 8);
        }
    }
    __syncthreads();
    int g = lane >> 2, c = lane & 3;
    int m0 = (w & 3) * 16, ns = (w >> 2) * 128;
    unsigned abase = smem_u32(At);
    unsigned wbase = smem_u32(Wt);
    int rowA = m0 + (lane & 7) + ((lane >> 3) & 1) * 8;
    int colA = ((lane >> 4) & 1) * 8;
    // B ldmatrix lane mapping: quadrant q -> {nt/nt+1} x {k0/k8}
    int bq = lane >> 3, br = lane & 7;
    int bj_off = br + ((bq >> 1) << 3);    // +8 rows for second nt tile
    int bk_off = (bq & 1) << 3;            // +8 k for b1 halves
    float acc[16][4];
#pragma unroll
    for (int nt = 0; nt < 16; nt++)
#pragma unroll
        for (int i = 0; i < 4; i++) acc[nt][i] = 0.f;
#pragma unroll
    for (int kt = 0; kt < 4; kt++) {           // K=64
        unsigned a0, a1, a2, a3;
        LDSM4(a0, a1, a2, a3, abase + (unsigned)(rowA * SXA + kt * 16 + colA) * 2u);
#pragma unroll
        for (int nt = 0; nt < 16; nt += 2) {
            unsigned b0, b1, b2, b3;
            LDSM4(b0, b1, b2, b3,
                  wbase + (unsigned)((ns + nt * 8 + bj_off) * SXA + kt * 16 + bk_off) * 2u);
            MMA16816(acc[nt],     a0, a1, a2, a3, b0, b1);
            MMA16816(acc[nt + 1], a0, a1, a2, a3, b2, b3);
        }
    }
    __syncthreads();                           // A/W reads done; reuse pool for xh tile
#pragma unroll
    for (int nt = 0; nt < 16; nt++) {
        int col = ns + nt * 8 + 2 * c;
        *(__half2*)(pool + (m0 + g) * SXH + col)     = __floats2half2_rn(acc[nt][0], acc[nt][1]);
        *(__half2*)(pool + (m0 + 8 + g) * SXH + col) = __floats2half2_rn(acc[nt][2], acc[nt][3]);
    }
    __syncthreads();
    // vectorized xh store
    for (int i = t; i < 64 * 32; i += 256) {
        int row = i >> 5, c8 = i & 31;
        if (n0 + row < N_NODES)
            *(uint4*)(g_xh_h + (size_t)(n0 + row) * HC + c8 * 8) =
                *(const uint4*)(pool + row * SXH + c8 * 8);
    }
    // a_s/a_d: one thread per (node, head)
    {
        int node = t >> 2, hh = t & 3;
        const __half* rowp = pool + node * SXH + hh * 64;
        float s = 0.f, d = 0.f;
#pragma unroll
        for (int q = 0; q < 8; q++) {
            uint4 v = *(const uint4*)(rowp + q * 8);
            const __half2* hp = (const __half2*)&v;
#pragma unroll
            for (int u = 0; u < 4; u++) {
                float2 f = __half22float2(hp[u]);
                int col = hh * 64 + q * 8 + u * 2;
                s = fmaf(f.x, sAs[col], s); s = fmaf(f.y, sAs[col + 1], s);
                d = fmaf(f.x, sAd[col], d); d = fmaf(f.y, sAd[col + 1], d);
            }
        }
        if (n0 + node < N_NODES) {
            g_as[(size_t)(n0 + node) * NH + hh] = s;
            g_ad[(size_t)(n0 + node) * NH + hh] = d;
        }
    }
}

// GAT aggregation: one warp per dst node, online softmax, batch-max rescale.
#define GAT_ACCUM(WG, V) do {                                                     \
    const __half2* hp = (const __half2*)&(V);                                     \
    float2 f0 = __half22float2(hp[0]), f1 = __half22float2(hp[1]);                \
    float2 f2 = __half22float2(hp[2]), f3 = __half22float2(hp[3]);                \
    a0 = fmaf(WG, f0.x, a0); a1 = fmaf(WG, f0.y, a1);                             \
    a2 = fmaf(WG, f1.x, a2); a3 = fmaf(WG, f1.y, a3);                             \
    a4 = fmaf(WG, f2.x, a4); a5 = fmaf(WG, f2.y, a5);                             \
    a6 = fmaf(WG, f3.x, a6); a7 = fmaf(WG, f3.y, a7);                             \
} while (0)

#define GAT_EDGE(Q, V) do {                                                       \
    float e = (Q) + ad; e = e > 0.f ? e : 0.2f * e;                               \
    if (e > m) {                                                                  \
        float corr = __expf(m - e);                                               \
        m = e; z *= corr;                                                         \
        a0 *= corr; a1 *= corr; a2 *= corr; a3 *= corr;                           \
        a4 *= corr; a5 *= corr; a6 *= corr; a7 *= corr;                           \
    }                                                                             \
    float wg = __expf(e - m);                                                     \
    z += wg;                                                                      \
    GAT_ACCUM(wg, V);                                                             \
} while (0)

__global__ void k_gat(const float* __restrict__ bc) {
    int w = (blockIdx.x * blockDim.x + threadIdx.x) >> 5;
    if (w >= N_NODES) return;
    int lane = threadIdx.x & 31;
    int hh = lane >> 3;                  // head owning channels [lane*8, lane*8+8)
    int beg = g_off[w], end = g_off[w + 1];
    float ad = g_ad[w * NH + hh];
    float m = -INFINITY, z = 0.f;
    float a0 = 0, a1 = 0, a2 = 0, a3 = 0, a4 = 0, a5 = 0, a6 = 0, a7 = 0;
    int p = beg;
    for (; p + 4 <= end; p += 4) {       // MLP=4 front-batched, single rescale
        int s0 = g_srcl[p], s1 = g_srcl[p + 1], s2 = g_srcl[p + 2], s3 = g_srcl[p + 3];
        float q0 = g_as[s0 * NH + hh];
        float q1 = g_as[s1 * NH + hh];
        float q2 = g_as[s2 * NH + hh];
        float q3 = g_as[s3 * NH + hh];
        uint4 v0 = *(const uint4*)(g_xh_h + (size_t)s0 * HC + lane * 8);
        uint4 v1 = *(const uint4*)(g_xh_h + (size_t)s1 * HC + lane * 8);
        uint4 v2 = *(const uint4*)(g_xh_h + (size_t)s2 * HC + lane * 8);
        uint4 v3 = *(const uint4*)(g_xh_h + (size_t)s3 * HC + lane * 8);
        float e0 = q0 + ad; e0 = e0 > 0.f ? e0 : 0.2f * e0;
        float e1 = q1 + ad; e1 = e1 > 0.f ? e1 : 0.2f * e1;
        float e2 = q2 + ad; e2 = e2 > 0.f ? e2 : 0.2f * e2;
        float e3 = q3 + ad; e3 = e3 > 0.f ? e3 : 0.2f * e3;
        float eb = fmaxf(fmaxf(e0, e1), fmaxf(e2, e3));
        if (eb > m) {
            float corr = __expf(m - eb);
            m = eb; z *= corr;
            a0 *= corr; a1 *= corr; a2 *= corr; a3 *= corr;
            a4 *= corr; a5 *= corr; a6 *= corr; a7 *= corr;
        }
        float w0 = __expf(e0 - m), w1 = __expf(e1 - m);
        float w2 = __expf(e2 - m), w3 = __expf(e3 - m);
        z += w0 + w1 + w2 + w3;
        GAT_ACCUM(w0, v0);
        GAT_ACCUM(w1, v1);
        GAT_ACCUM(w2, v2);
        GAT_ACCUM(w3, v3);
    }
    for (; p < end; p++) {
        int s0 = g_srcl[p];
        float q0 = g_as[s0 * NH + hh];
        uint4 v0 = *(const uint4*)(g_xh_h + (size_t)s0 * HC + lane * 8);
        GAT_EDGE(q0, v0);
    }
    float inv = 1.f / (z + 1e-16f);
    const float4* bcv = (const float4*)(bc + lane * 8);
    float4 c0 = bcv[0], c1 = bcv[1];
    __half2 q[4];
    q[0] = __floats2half2_rn(fmaf(a0, inv, c0.x), fmaf(a1, inv, c0.y));
    q[1] = __floats2half2_rn(fmaf(a2, inv, c0.z), fmaf(a3, inv, c0.w));
    q[2] = __floats2half2_rn(fmaf(a4, inv, c1.x), fmaf(a5, inv, c1.y));
    q[3] = __floats2half2_rn(fmaf(a6, inv, c1.z), fmaf(a7, inv, c1.w));
    *(uint4*)(g_out_h + (size_t)w * HC + lane * 8) = *(uint4*)q;
}

// ====== fused FFN via tensor cores (validated R11) =============================
#define SRA 264   // smem halves stride for X
#define SFB 136   // smem halves stride for ff
__global__ void __launch_bounds__(256, 2)
k_ffn(int l, const float* __restrict__ b1, const float* __restrict__ b2,
      const float* __restrict__ lng, const float* __restrict__ lnb,
      float* __restrict__ h) {
    int t = threadIdx.x, lane = t & 31, w = t >> 5;
    int n0 = blockIdx.x * 64;
    __shared__ __align__(16) __half pool_h[64 * SRA];  // 33 KB, staged
    __shared__ float2 stats[64];
    for (int i = t; i < 64 * 32; i += 256) {
        int row = i >> 5, c8 = i & 31;
        *(uint4*)(pool_h + row * SRA + c8 * 8) =
            *(const uint4*)(g_out_h + (size_t)(n0 + row) * HC + c8 * 8);
    }
    __syncthreads();
    int g = lane >> 2, c = lane & 3;
    int m0 = (w & 3) * 16;
    int nsA = (w >> 2) * 64;
    unsigned xbase = smem_u32(pool_h);
    int rowA = m0 + (lane & 7) + ((lane >> 3) & 1) * 8;
    int colA = ((lane >> 4) & 1) * 8;
    float acc[8][4];
#pragma unroll
    for (int nt = 0; nt < 8; nt++)
#pragma unroll
        for (int i = 0; i < 4; i++) acc[nt][i] = 0.f;
    const __half* W1h = g_W1h + (size_t)l * DFF * HC;
#pragma unroll 1
    for (int kt = 0; kt < 16; kt++) {
        unsigned a0, a1, a2, a3;
        LDSM4(a0, a1, a2, a3, xbase + (unsigned)(rowA * SRA + kt * 16 + colA) * 2u);
#pragma unroll
        for (int nt = 0; nt < 8; nt++) {
            const __half* bp = W1h + (size_t)(nsA + nt * 8 + g) * HC + kt * 16 + 2 * c;
            unsigned b0 = *(const unsigned*)bp;
            unsigned b1r = *(const unsigned*)(bp + 8);
            MMA16816(acc[nt], a0, a1, a2, a3, b0, b1r);
        }
    }
    __syncthreads();
    __half* ff = pool_h;
#pragma unroll
    for (int nt = 0; nt < 8; nt++) {
        int col = nsA + nt * 8 + 2 * c;
        float bA = b1[col], bB = b1[col + 1];
        float v0 = acc[nt][0] + bA, v1 = acc[nt][1] + bB;
        float v2 = acc[nt][2] + bA, v3 = acc[nt][3] + bB;
        float g0 = 0.5f * v0 * (1.0f + erff(v0 * 0.70710678118654752f));
        float g1 = 0.5f * v1 * (1.0f + erff(v1 * 0.70710678118654752f));
        float g2 = 0.5f * v2 * (1.0f + erff(v2 * 0.70710678118654752f));
        float g3 = 0.5f * v3 * (1.0f + erff(v3 * 0.70710678118654752f));
        *(__half2*)(ff + (m0 + g) * SFB + col)     = __floats2half2_rn(g0, g1);
        *(__half2*)(ff + (m0 + 8 + g) * SFB + col) = __floats2half2_rn(g2, g3);
    }
    __syncthreads();
    int nsB = (w >> 2) * 32;
    int rowB = m0 + (lane & 7) + ((lane >> 3) & 1) * 8;
    int colB = ((lane >> 4) & 1) * 8;
    float acc2[4][4];
#pragma unroll
    for (int nt = 0; nt < 4; nt++)
#pragma unroll
        for (int i = 0; i < 4; i++) acc2[nt][i] = 0.f;
    const __half* W2h = g_W2h + (size_t)l * HID * DFF;
#pragma unroll 1
    for (int kt = 0; kt < 8; kt++) {
        unsigned a0, a1, a2, a3;
        LDSM4(a0, a1, a2, a3, xbase + (unsigned)(rowB * SFB + kt * 16 + colB) * 2u);
#pragma unroll
        for (int nt = 0; nt < 4; nt++) {
            const __half* bp = W2h + (size_t)(nsB + nt * 8 + g) * DFF + kt * 16 + 2 * c;
            unsigned b0 = *(const unsigned*)bp;
            unsigned b1r = *(const unsigned*)(bp + 8);
            MMA16816(acc2[nt], a0, a1, a2, a3, b0, b1r);
        }
    }
    __syncthreads();
    float* sln = (float*)pool_h;         // 64 x 65 f32
#pragma unroll
    for (int nt = 0; nt < 4; nt++) {
        int col = nsB + nt * 8 + 2 * c;
        float bA = b2[col], bB = b2[col + 1];
        sln[(m0 + g) * 65 + col]         = acc2[nt][0] + bA;
        sln[(m0 + g) * 65 + col + 1]     = acc2[nt][1] + bB;
        sln[(m0 + 8 + g) * 65 + col]     = acc2[nt][2] + bA;
        sln[(m0 + 8 + g) * 65 + col + 1] = acc2[nt][3] + bB;
    }
    __syncthreads();
    int node = t >> 2, part = t & 3;
    float s = 0.f, sq = 0.f;
#pragma unroll
    for (int k = 0; k < 16; k++) {
        float v = sln[node * 65 + part * 16 + k];
        s += v; sq = fmaf(v, v, sq);
    }
    s  += __shfl_xor_sync(0xffffffffu, s, 1);  s  += __shfl_xor_sync(0xffffffffu, s, 2);
    sq += __shfl_xor_sync(0xffffffffu, sq, 1); sq += __shfl_xor_sync(0xffffffffu, sq, 2);
    if (part == 0) {
        float mean = s * (1.f / 64.f);
        stats[node] = make_float2(mean, sq * (1.f / 64.f) - mean * mean);
    }
    __syncthreads();
    if (n0 + node < N_NODES) {
        float2 st = stats[node];
        float rinv = rsqrtf(st.y + 1e-5f);
#pragma unroll
        for (int k = 0; k < 16; k++) {
            int col = part * 16 + k;
            float nv = (sln[node * 65 + col] - st.x) * rinv * lng[col] + lnb[col];
            h[(size_t)(n0 + node) * HID + col] += nv;
        }
    }
}

// ================= driver ======================================================
extern "C" void kernel_launch(void* const* d_in, const int* in_sizes, int n_in,
                              void* d_out, int out_size) {
    const float* x       = (const float*)d_in[0];
    const int*   ei      = (const int*)  d_in[1];
    const float* We      = (const float*)d_in[2];
    const float* be      = (const float*)d_in[3];
    const float* Wc      = (const float*)d_in[4];
    const float* att_src = (const float*)d_in[5];
    const float* att_dst = (const float*)d_in[6];
    const float* bc      = (const float*)d_in[7];
    const float* W1      = (const float*)d_in[8];
    const float* b1      = (const float*)d_in[9];
    const float* W2      = (const float*)d_in[10];
    const float* b2      = (const float*)d_in[11];
    const float* ln_g    = (const float*)d_in[12];
    const float* ln_b    = (const float*)d_in[13];

    float* h = (float*)d_out;

    // k_xh_att stays the profiled (4th) launch.
    k_wprep    <<<896, 256>>>(W1, W2, Wc);                     // 1
    k_csr_init <<<(N_NODES + 255) / 256, 256>>>();             // 2
    k_embed    <<<1250, 256>>>(x, We, be, h);                  // 3
    k_xh_att   <<<313, 256>>>(h, 0, att_src, att_dst);         // 4 (layer 0)
    k_csr_count<<<(E_EDGES + 255) / 256, 256>>>(ei);           // 5
    k_csr_scan <<<1, 1024>>>();                                // 6
    k_csr_fill <<<(ET + 255) / 256, 256>>>(ei);                // 7
    k_gat      <<<2500, 256>>>(bc);                            // 8 (layer 0)
    k_ffn      <<<313, 256>>>(0, b1, b2, ln_g, ln_b, h);       // 9 (layer 0)

    for (int l = 1; l < NL; l++) {
        k_xh_att<<<313, 256>>>(h, l, att_src + l * NH * C, att_dst + l * NH * C);
        k_gat   <<<2500, 256>>>(bc + l * HC);
        k_ffn   <<<313, 256>>>(l, b1 + l * DFF, b2 + l * HID,
                               ln_g + l * HID, ln_b + l * HID, h);
    }
}